// round 9
// baseline (speedup 1.0000x reference)
#include <cuda_runtime.h>
#include <math.h>

#define CSTEP 8
#define CSTEP2 4

// Scratch (fp32): feat/outs/gates + hoisted x-part conv results
__device__ float g_scratch[139853824];

__device__ __forceinline__ float sigf(float x) { return 1.f / (1.f + __expf(-x)); }
__device__ __forceinline__ float ftanh(float x) {
    float e = __expf(2.f * x);
    return 1.f - 2.f / (e + 1.f);
}

// ---------------------------------------------------------------------------
// Unified 3x3 stride-1 conv core, 2x2 pixels x NCO couts per thread.
// Tile: 16 rows x TILEW cols. Block: (TILEW/2, 8) = TILEW*4 threads.
// MODE 2: plain conv over Cin=Cx channels of `in`, out = acc + bias (preBias).
// MODE 0: gates. in=hprev (Cin=Ch), seeded by pre (preBias), sigmoid -> out.
// MODE 1: cand. in=hprev, loader multiplies by r (gatesIn), GRU update -> out.
// grid: (N * Cout/NCO, H/16, W/TILEW)
// ---------------------------------------------------------------------------
template<int TILEW, int NCO, int MODE>
__global__ __launch_bounds__(TILEW * 4)
void convk(const float* __restrict__ in, const float* __restrict__ Wt,
           const float* __restrict__ preBias, const float* __restrict__ gatesIn,
           float* __restrict__ out,
           int Cx, int CinTot, int Cin, int Cout, int H, int W)
{
    constexpr int NT   = TILEW * 4;
    constexpr int LWD  = TILEW + 2;
    constexpr int SSTR = TILEW + 4;
    constexpr int WPB  = NT / 32;      // warps per block
    constexpr int CPW  = CSTEP / WPB;  // channels per warp in loader

    const int cgrp = Cout / NCO;
    int n   = blockIdx.x / cgrp;
    int co0 = (blockIdx.x % cgrp) * NCO;
    int oy0 = blockIdx.y * 16;
    int ox0 = blockIdx.z * TILEW;
    int tx = threadIdx.x, ty = threadIdx.y;
    int tid  = ty * (TILEW / 2) + tx;
    int lane = tid & 31, warp = tid >> 5;

    __shared__ float tile[CSTEP][18][SSTR];
    __shared__ __align__(16) float ws[CSTEP][NCO][12];

    int HW = H * W;
    // loader column predicates (row-invariant, hoisted)
    bool okx0 = (lane < LWD) && ((unsigned)(ox0 - 1 + lane) < (unsigned)W);
    bool okx1 = (LWD > 32) && ((lane + 32) < LWD)
                && ((unsigned)(ox0 + 31 + lane) < (unsigned)W);

    const int WOFF = (MODE == 2) ? 0 : Cx;

    float acc[NCO][2][2];
#pragma unroll
    for (int co = 0; co < NCO; co++)
#pragma unroll
        for (int r = 0; r < 2; r++) { acc[co][r][0] = 0.f; acc[co][r][1] = 0.f; }

    for (int ci0 = 0; ci0 < Cin; ci0 += CSTEP) {
        __syncthreads();
        // ---- loader: warp handles CPW channel planes, row loop, no div/mod
#pragma unroll
        for (int k = 0; k < CPW; k++) {
            int c  = warp * CPW + k;
            int ch = ci0 + c;
            const float* q  = in + ((size_t)n * Cin + ch) * HW
                              + (size_t)(oy0 - 1) * W + (ox0 - 1);
            const float* qr = nullptr;
            if (MODE == 1)
                qr = gatesIn + ((size_t)n * 2 * Cin + ch) * HW
                     + (size_t)(oy0 - 1) * W + (ox0 - 1);
#pragma unroll
            for (int r = 0; r < 18; r++) {
                int gy = oy0 - 1 + r;
                bool oky = (unsigned)gy < (unsigned)H;
                float v0 = 0.f;
                if (oky && okx0) {
                    v0 = q[lane];
                    if (MODE == 1) v0 *= qr[lane];
                }
                if (lane < LWD) tile[c][r][lane] = v0;
                if (LWD > 32) {
                    if ((lane + 32) < LWD) {
                        float v1 = 0.f;
                        if (oky && okx1) {
                            v1 = q[lane + 32];
                            if (MODE == 1) v1 *= qr[lane + 32];
                        }
                        tile[c][r][lane + 32] = v1;
                    }
                }
                q += W;
                if (MODE == 1) qr += W;
            }
        }
        // ---- weights: CSTEP x NCO x 9
        for (int i = tid; i < CSTEP * NCO * 9; i += NT) {
            int c = i / (NCO * 9), rem = i % (NCO * 9);
            int co = rem / 9, kk = rem % 9;
            ws[c][co][kk] = Wt[((size_t)(co0 + co) * CinTot + WOFF + ci0 + c) * 9 + kk];
        }
        __syncthreads();

        // ---- compute: 2x2 pixels x NCO couts
#pragma unroll
        for (int c = 0; c < CSTEP; c++) {
            float a4[4][4];
#pragma unroll
            for (int r = 0; r < 4; r++) {
                float2 pA = *(const float2*)&tile[c][2 * ty + r][2 * tx];
                float2 pB = *(const float2*)&tile[c][2 * ty + r][2 * tx + 2];
                a4[r][0] = pA.x; a4[r][1] = pA.y; a4[r][2] = pB.x; a4[r][3] = pB.y;
            }
#pragma unroll
            for (int co = 0; co < NCO; co++) {
                float4 wa = *(const float4*)&ws[c][co][0];
                float4 wb = *(const float4*)&ws[c][co][4];
                float w8  = ws[c][co][8];
                float w[9] = {wa.x, wa.y, wa.z, wa.w, wb.x, wb.y, wb.z, wb.w, w8};
#pragma unroll
                for (int i = 0; i < 3; i++) {
#pragma unroll
                    for (int j = 0; j < 3; j++) {
                        float wv = w[i * 3 + j];
                        acc[co][0][0] = fmaf(a4[i][j],         wv, acc[co][0][0]);
                        acc[co][0][1] = fmaf(a4[i][j + 1],     wv, acc[co][0][1]);
                        acc[co][1][0] = fmaf(a4[i + 1][j],     wv, acc[co][1][0]);
                        acc[co][1][1] = fmaf(a4[i + 1][j + 1], wv, acc[co][1][1]);
                    }
                }
            }
        }
    }

    int oy = oy0 + 2 * ty, ox = ox0 + 2 * tx;
    if (MODE == 2) {
#pragma unroll
        for (int co = 0; co < NCO; co++) {
            float bz = preBias[co0 + co];
            float* op = out + ((size_t)n * Cout + co0 + co) * HW + (size_t)oy * W + ox;
            float2 f0 = {acc[co][0][0] + bz, acc[co][0][1] + bz};
            float2 f1 = {acc[co][1][0] + bz, acc[co][1][1] + bz};
            *(float2*)op = f0;
            *(float2*)(op + W) = f1;
        }
    } else if (MODE == 0) {
#pragma unroll
        for (int co = 0; co < NCO; co++) {
            const float* pp = preBias + ((size_t)n * Cout + co0 + co) * HW
                              + (size_t)oy * W + ox;
            float2 p0 = *(const float2*)pp, p1 = *(const float2*)(pp + W);
            float* op = out + ((size_t)n * Cout + co0 + co) * HW + (size_t)oy * W + ox;
            float2 f0 = {sigf(acc[co][0][0] + p0.x), sigf(acc[co][0][1] + p0.y)};
            float2 f1 = {sigf(acc[co][1][0] + p1.x), sigf(acc[co][1][1] + p1.y)};
            *(float2*)op = f0;
            *(float2*)(op + W) = f1;
        }
    } else {
#pragma unroll
        for (int co = 0; co < NCO; co++) {
            int cc = co0 + co;
            const float* pp = preBias + ((size_t)n * Cout + cc) * HW
                              + (size_t)oy * W + ox;
            float2 p0 = *(const float2*)pp, p1 = *(const float2*)(pp + W);
            const float* zp = gatesIn + ((size_t)n * 2 * Cin + Cin + cc) * HW
                              + (size_t)oy * W + ox;
            float2 z0 = *(const float2*)zp, z1 = *(const float2*)(zp + W);
            const float* hp = in + ((size_t)n * Cin + cc) * HW + (size_t)oy * W + ox;
            float2 h0 = *(const float2*)hp, h1 = *(const float2*)(hp + W);
            float* op = out + ((size_t)n * Cin + cc) * HW + (size_t)oy * W + ox;
            float2 f0, f1;
            f0.x = z0.x * h0.x + (1.f - z0.x) * ftanh(acc[co][0][0] + p0.x);
            f0.y = z0.y * h0.y + (1.f - z0.y) * ftanh(acc[co][0][1] + p0.y);
            f1.x = z1.x * h1.x + (1.f - z1.x) * ftanh(acc[co][1][0] + p1.x);
            f1.y = z1.y * h1.y + (1.f - z1.y) * ftanh(acc[co][1][1] + p1.y);
            *(float2*)op = f0;
            *(float2*)(op + W) = f1;
        }
    }
}

// ---------------------------------------------------------------------------
// t = 0 step (h == 0): hn = (1 - sigmoid(z_pre)) * tanh(c_pre), elementwise.
// ---------------------------------------------------------------------------
__global__ void gru_t0(const float* __restrict__ gz, const float* __restrict__ gc,
                       float* __restrict__ hn, int Ch, int HW, int total)
{
    int i = blockIdx.x * 256 + threadIdx.x;
    if (i >= total) return;
    int b = i / (Ch * HW);
    float z = sigf(gz[(size_t)i + (size_t)(b + 1) * Ch * HW]);
    hn[i] = (1.f - z) * ftanh(gc[i]);
}

// ---------------------------------------------------------------------------
// Stride-2 3x3 conv (pad 1) + leaky relu(0.2), over all N = T*B samples.
// ---------------------------------------------------------------------------
__global__ void conv_s2_lrelu(const float* __restrict__ in, const float* __restrict__ Wt,
                              const float* __restrict__ bias, float* __restrict__ out,
                              int Cin, int Cout, int Hin, int Win, int sOuter, int sInner)
{
    int coutBlocks = Cout >> 3;
    int n  = blockIdx.x / coutBlocks;
    int cb = blockIdx.x % coutBlocks;
    int co0 = cb * 8;
    int t = n / 8, b = n % 8;
    const float* inN = in + (size_t)t * sOuter + (size_t)b * sInner;
    int Hout = Hin >> 1, Wout = Win >> 1;
    int oy0 = blockIdx.y * 16, ox0 = blockIdx.z * 16;
    int tx = threadIdx.x, ty = threadIdx.y;
    int tid = ty * 16 + tx;

    __shared__ float tile[CSTEP2][33][35];
    __shared__ float ws[CSTEP2][8][9];

    float acc0[8], acc1[8];
#pragma unroll
    for (int i = 0; i < 8; i++) { acc0[i] = 0.f; acc1[i] = 0.f; }

    for (int ci0 = 0; ci0 < Cin; ci0 += CSTEP2) {
        __syncthreads();
        for (int i = tid; i < CSTEP2 * 1089; i += 128) {
            int c = i / 1089, p = i % 1089;
            int ly = p / 33, lx = p % 33;
            int gy = 2 * oy0 - 1 + ly, gx = 2 * ox0 - 1 + lx;
            float v = 0.f;
            int ci = ci0 + c;
            if (ci < Cin && gy >= 0 && gy < Hin && gx >= 0 && gx < Win)
                v = inN[((size_t)ci * Hin + gy) * Win + gx];
            tile[c][ly][lx] = v;
        }
        for (int i = tid; i < CSTEP2 * 72; i += 128) {
            int c = i / 72, r = i % 72;
            int co = r / 9, k = r % 9;
            float wv = 0.f;
            if (ci0 + c < Cin)
                wv = Wt[((size_t)(co0 + co) * Cin + (ci0 + c)) * 9 + k];
            ws[c][co][k] = wv;
        }
        __syncthreads();

#pragma unroll
        for (int c = 0; c < CSTEP2; c++) {
            float a[5][3];
#pragma unroll
            for (int i = 0; i < 5; i++)
#pragma unroll
                for (int j = 0; j < 3; j++)
                    a[i][j] = tile[c][4 * ty + i][2 * tx + j];
#pragma unroll
            for (int co = 0; co < 8; co++) {
                float w0 = ws[c][co][0], w1 = ws[c][co][1], w2 = ws[c][co][2];
                float w3 = ws[c][co][3], w4 = ws[c][co][4], w5 = ws[c][co][5];
                float w6 = ws[c][co][6], w7 = ws[c][co][7], w8 = ws[c][co][8];
                acc0[co] += a[0][0]*w0 + a[0][1]*w1 + a[0][2]*w2
                          + a[1][0]*w3 + a[1][1]*w4 + a[1][2]*w5
                          + a[2][0]*w6 + a[2][1]*w7 + a[2][2]*w8;
                acc1[co] += a[2][0]*w0 + a[2][1]*w1 + a[2][2]*w2
                          + a[3][0]*w3 + a[3][1]*w4 + a[3][2]*w5
                          + a[4][0]*w6 + a[4][1]*w7 + a[4][2]*w8;
            }
        }
    }

    int oy = oy0 + 2 * ty, ox = ox0 + tx;
#pragma unroll
    for (int co = 0; co < 8; co++) {
        float bz = bias[co0 + co];
        float v0 = acc0[co] + bz, v1 = acc1[co] + bz;
        v0 = v0 > 0.f ? v0 : 0.2f * v0;
        v1 = v1 > 0.f ? v1 : 0.2f * v1;
        size_t o = (((size_t)n * Cout + co0 + co) * Hout + oy) * Wout + ox;
        out[o]        = v0;
        out[o + Wout] = v1;
    }
}

extern "C" void kernel_launch(void* const* d_in, const int* in_sizes, int n_in,
                              void* d_out, int out_size)
{
    const float* x   = (const float*)d_in[0];
    const float* W1  = (const float*)d_in[1];
    const float* b1  = (const float*)d_in[2];
    const float* Wg1 = (const float*)d_in[3];
    const float* bg1 = (const float*)d_in[4];
    const float* Wc1 = (const float*)d_in[5];
    const float* bc1 = (const float*)d_in[6];
    const float* W2  = (const float*)d_in[7];
    const float* b2  = (const float*)d_in[8];
    const float* Wg2 = (const float*)d_in[9];
    const float* bg2 = (const float*)d_in[10];
    const float* Wc2 = (const float*)d_in[11];
    const float* bc2 = (const float*)d_in[12];
    const float* W3  = (const float*)d_in[13];
    const float* b3  = (const float*)d_in[14];
    const float* Wg3 = (const float*)d_in[15];
    const float* bg3 = (const float*)d_in[16];
    const float* Wc3 = (const float*)d_in[17];
    const float* bc3 = (const float*)d_in[18];

    float* base = nullptr;
    cudaGetSymbolAddress((void**)&base, g_scratch);

    float* feat1 = base;                   // 10*8*16*64*64  = 5,242,880
    float* outs1 = base + 5242880;         // 10*8*64*64*64  = 20,971,520
    float* feat2 = base + 26214400;        // 10*8*64*32*32  = 5,242,880
    float* outs2 = base + 31457280;        // 10*8*96*32*32  = 7,864,320
    float* feat3 = base + 39321600;        // 10*8*96*16*16  = 1,966,080
    float* outs3 = base + 41287680;        // 10*8*96*16*16  = 1,966,080
    float* gates = base + 43253760;        // 8*192*64*64 max -> 4,194,304
    float* gxg1  = base + 47448064;        // 80*128*4096 = 41,943,040
    float* gxc1  = base + 89391104;        // 80*64*4096  = 20,971,520
    float* gxg2  = base + 110362624;       // 80*192*1024 = 15,728,640
    float* gxc2  = base + 126091264;       // 80*96*1024  =  7,864,320
    float* gxg3  = base + 133955584;       // 80*192*256  =  3,932,160
    float* gxc3  = base + 137887744;       // 80*96*256   =  1,966,080

    dim3 blkc(16, 8);
    dim3 blkW(16, 8);    // TILEW=32
    dim3 blkN(8, 8);     // TILEW=16

    // ================= Stage 1 (H=W=64, Cx=16, Ch=64) =================
    conv_s2_lrelu<<<dim3(80 * 2, 4, 4), blkc>>>(x, W1, b1, feat1,
                                                1, 16, 128, 128, 16384, 163840);
    convk<32, 8, 2><<<dim3(80 * 16, 4, 2), blkW>>>(feat1, Wg1, bg1, nullptr, gxg1,
                                                   0, 80, 16, 128, 64, 64);
    convk<32, 8, 2><<<dim3(80 * 8, 4, 2), blkW>>>(feat1, Wc1, bc1, nullptr, gxc1,
                                                  0, 80, 16, 64, 64, 64);
    gru_t0<<<(8 * 64 * 4096 + 255) / 256, 256>>>(gxg1, gxc1, outs1, 64, 4096, 8 * 64 * 4096);
    for (int t = 1; t < 10; t++) {
        const float* hp = outs1 + (size_t)(t - 1) * 8 * 64 * 4096;
        float* hn = outs1 + (size_t)t * 8 * 64 * 4096;
        convk<32, 8, 0><<<dim3(8 * 16, 4, 2), blkW>>>(hp, Wg1,
                gxg1 + (size_t)t * 8 * 128 * 4096, nullptr, gates,
                16, 80, 64, 128, 64, 64);
        convk<32, 8, 1><<<dim3(8 * 8, 4, 2), blkW>>>(hp, Wc1,
                gxc1 + (size_t)t * 8 * 64 * 4096, gates, hn,
                16, 80, 64, 64, 64, 64);
    }

    // ================= Stage 2 (H=W=32, Cx=64, Ch=96) =================
    conv_s2_lrelu<<<dim3(80 * 8, 2, 2), blkc>>>(outs1, W2, b2, feat2,
                                                64, 64, 64, 64, 8 * 64 * 4096, 64 * 4096);
    convk<32, 8, 2><<<dim3(80 * 24, 2, 1), blkW>>>(feat2, Wg2, bg2, nullptr, gxg2,
                                                   0, 160, 64, 192, 32, 32);
    convk<32, 8, 2><<<dim3(80 * 12, 2, 1), blkW>>>(feat2, Wc2, bc2, nullptr, gxc2,
                                                   0, 160, 64, 96, 32, 32);
    gru_t0<<<(8 * 96 * 1024 + 255) / 256, 256>>>(gxg2, gxc2, outs2, 96, 1024, 8 * 96 * 1024);
    for (int t = 1; t < 10; t++) {
        const float* hp = outs2 + (size_t)(t - 1) * 8 * 96 * 1024;
        float* hn = outs2 + (size_t)t * 8 * 96 * 1024;
        convk<32, 8, 0><<<dim3(8 * 24, 2, 1), blkW>>>(hp, Wg2,
                gxg2 + (size_t)t * 8 * 192 * 1024, nullptr, gates,
                64, 160, 96, 192, 32, 32);
        convk<32, 8, 1><<<dim3(8 * 12, 2, 1), blkW>>>(hp, Wc2,
                gxc2 + (size_t)t * 8 * 96 * 1024, gates, hn,
                64, 160, 96, 96, 32, 32);
    }

    // ================= Stage 3 (H=W=16, Cx=96, Ch=96) =================
    conv_s2_lrelu<<<dim3(80 * 12, 1, 1), blkc>>>(outs2, W3, b3, feat3,
                                                 96, 96, 32, 32, 8 * 96 * 1024, 96 * 1024);
    convk<16, 4, 2><<<dim3(80 * 48, 1, 1), blkN>>>(feat3, Wg3, bg3, nullptr, gxg3,
                                                   0, 192, 96, 192, 16, 16);
    convk<16, 4, 2><<<dim3(80 * 24, 1, 1), blkN>>>(feat3, Wc3, bc3, nullptr, gxc3,
                                                   0, 192, 96, 96, 16, 16);
    gru_t0<<<(8 * 96 * 256 + 255) / 256, 256>>>(gxg3, gxc3, outs3, 96, 256, 8 * 96 * 256);
    for (int t = 1; t < 10; t++) {
        const float* hp = outs3 + (size_t)(t - 1) * 8 * 96 * 256;
        float* hn = outs3 + (size_t)t * 8 * 96 * 256;
        convk<16, 4, 0><<<dim3(8 * 48, 1, 1), blkN>>>(hp, Wg3,
                gxg3 + (size_t)t * 8 * 192 * 256, nullptr, gates,
                96, 192, 96, 192, 16, 16);
        convk<16, 4, 1><<<dim3(8 * 24, 1, 1), blkN>>>(hp, Wc3,
                gxc3 + (size_t)t * 8 * 96 * 256, gates, hn,
                96, 192, 96, 96, 16, 16);
    }

    // ---------------- Assemble output: (h1, h2, h3) flattened ----------------
    float* out = (float*)d_out;
    cudaMemcpyAsync(out,
                    outs1 + 9UL * 8 * 64 * 4096,
                    (size_t)8 * 64 * 4096 * sizeof(float),
                    cudaMemcpyDeviceToDevice, 0);
    cudaMemcpyAsync(out + 2097152,
                    outs2 + 9UL * 8 * 96 * 1024,
                    (size_t)8 * 96 * 1024 * sizeof(float),
                    cudaMemcpyDeviceToDevice, 0);
    cudaMemcpyAsync(out + 2097152 + 786432,
                    outs3 + 9UL * 8 * 96 * 256,
                    (size_t)8 * 96 * 256 * sizeof(float),
                    cudaMemcpyDeviceToDevice, 0);
}

// round 10
// speedup vs baseline: 1.1344x; 1.1344x over previous
#include <cuda_runtime.h>
#include <math.h>

#define TS 16
#define CSTEP 8
#define CSTEP2 4

// Scratch (fp32): feat/outs/gates + hoisted x-part conv results
__device__ float g_scratch[139853824];

__device__ __forceinline__ float sigf(float x) { return 1.f / (1.f + __expf(-x)); }
__device__ __forceinline__ float ftanh(float x) {
    float e = __expf(2.f * x);
    return 1.f - 2.f / (e + 1.f);
}

// ---------------------------------------------------------------------------
// Batched stride-1 3x3 conv (pad 1), raw output + bias. N samples contiguous.
// in: (N, Cin, H, W), weights OIHW row stride CinTot, out: (N, Cout, H, W).
// block (16,8), 8 couts/block. grid: (N * Cout/8, H/16, W/16)
// ---------------------------------------------------------------------------
__global__ __launch_bounds__(128)
void conv_pre(const float* __restrict__ in, const float* __restrict__ Wt,
              const float* __restrict__ bias, float* __restrict__ out,
              int Cin, int CinTot, int Cout, int H, int W)
{
    int coutBlocks = Cout >> 3;
    int n   = blockIdx.x / coutBlocks;
    int co0 = (blockIdx.x % coutBlocks) * 8;
    int oy0 = blockIdx.y * TS;
    int ox0 = blockIdx.z * TS;
    int tx = threadIdx.x, ty = threadIdx.y;
    int tid = ty * 16 + tx;
    int lane = tid & 31, warp = tid >> 5;

    __shared__ float tile[CSTEP][18][19];
    __shared__ __align__(16) float ws[CSTEP][8][12];

    int HW = H * W;
    const float* inN = in + (size_t)n * Cin * HW;
    // loader: lane's column predicate (row-invariant)
    bool okc = (lane < 18) && ((unsigned)(ox0 - 1 + lane) < (unsigned)W);

    float acc0[8], acc1[8];
#pragma unroll
    for (int i = 0; i < 8; i++) { acc0[i] = 0.f; acc1[i] = 0.f; }

    for (int ci0 = 0; ci0 < Cin; ci0 += CSTEP) {
        __syncthreads();
        // div-free loader: warp handles 2 channel planes, 18 predicated rows each
#pragma unroll
        for (int k = 0; k < 2; k++) {
            int c = warp * 2 + k;
            const float* q = inN + (size_t)(ci0 + c) * HW
                             + (size_t)(oy0 - 1) * W + (ox0 - 1);
#pragma unroll
            for (int r = 0; r < 18; r++) {
                bool oky = (unsigned)(oy0 - 1 + r) < (unsigned)H;
                float v = 0.f;
                if (oky && okc) v = q[lane];
                if (lane < 18) tile[c][r][lane] = v;
                q += W;
            }
        }
        for (int i = tid; i < CSTEP * 72; i += 128) {
            int c = i / 72, r = i % 72;
            int co = r / 9, kk = r % 9;
            ws[c][co][kk] = Wt[((size_t)(co0 + co) * CinTot + (ci0 + c)) * 9 + kk];
        }
        __syncthreads();

#pragma unroll
        for (int c = 0; c < CSTEP; c++) {
            float a[4][3];
#pragma unroll
            for (int i = 0; i < 4; i++)
#pragma unroll
                for (int j = 0; j < 3; j++)
                    a[i][j] = tile[c][2 * ty + i][tx + j];
#pragma unroll
            for (int co = 0; co < 8; co++) {
                float4 wa = *(const float4*)&ws[c][co][0];
                float4 wb = *(const float4*)&ws[c][co][4];
                float w8  = ws[c][co][8];
                acc0[co] += a[0][0]*wa.x + a[0][1]*wa.y + a[0][2]*wa.z
                          + a[1][0]*wa.w + a[1][1]*wb.x + a[1][2]*wb.y
                          + a[2][0]*wb.z + a[2][1]*wb.w + a[2][2]*w8;
                acc1[co] += a[1][0]*wa.x + a[1][1]*wa.y + a[1][2]*wa.z
                          + a[2][0]*wa.w + a[2][1]*wb.x + a[2][2]*wb.y
                          + a[3][0]*wb.z + a[3][1]*wb.w + a[3][2]*w8;
            }
        }
    }

    int oy = oy0 + 2 * ty, ox = ox0 + tx;
#pragma unroll
    for (int co = 0; co < 8; co++) {
        float bz = bias[co0 + co];
        size_t o = ((size_t)n * Cout + co0 + co) * HW + (size_t)oy * W + ox;
        out[o]     = acc0[co] + bz;
        out[o + W] = acc1[co] + bz;
    }
}

// ---------------------------------------------------------------------------
// Recurrent h-part conv (t >= 1). Conv over Ch channels of hprev (mode 1:
// multiplied by r from gatesIn), seeded by pre (= bias + x-part).
// mode 0: gates -> sigmoid.  mode 1: cand -> GRU update.
// grid: (B * Cout/8, H/16, W/16)
// ---------------------------------------------------------------------------
__global__ __launch_bounds__(128)
void gru_conv_h(const float* __restrict__ hprev, const float* __restrict__ Wt,
                const float* __restrict__ pre, const float* __restrict__ gatesIn,
                float* __restrict__ out,
                int Cx, int CinTot, int Ch, int Cout, int H, int W, int mode)
{
    int coutBlocks = Cout >> 3;
    int b   = blockIdx.x / coutBlocks;
    int co0 = (blockIdx.x % coutBlocks) * 8;
    int oy0 = blockIdx.y * TS;
    int ox0 = blockIdx.z * TS;
    int tx = threadIdx.x, ty = threadIdx.y;
    int tid = ty * 16 + tx;
    int lane = tid & 31, warp = tid >> 5;

    __shared__ float tile[CSTEP][18][19];
    __shared__ __align__(16) float ws[CSTEP][8][12];

    int HW = H * W;
    bool okc = (lane < 18) && ((unsigned)(ox0 - 1 + lane) < (unsigned)W);

    float acc0[8], acc1[8];
#pragma unroll
    for (int i = 0; i < 8; i++) { acc0[i] = 0.f; acc1[i] = 0.f; }

    for (int ci0 = 0; ci0 < Ch; ci0 += CSTEP) {
        __syncthreads();
        // div-free loader: warp handles 2 channel planes of hprev (x r in mode 1)
        if (mode) {
#pragma unroll
            for (int k = 0; k < 2; k++) {
                int c = warp * 2 + k;
                int ch = ci0 + c;
                const float* q  = hprev + ((size_t)b * Ch + ch) * HW
                                  + (size_t)(oy0 - 1) * W + (ox0 - 1);
                const float* qr = gatesIn + ((size_t)b * 2 * Ch + ch) * HW
                                  + (size_t)(oy0 - 1) * W + (ox0 - 1);
#pragma unroll
                for (int r = 0; r < 18; r++) {
                    bool oky = (unsigned)(oy0 - 1 + r) < (unsigned)H;
                    float v = 0.f;
                    if (oky && okc) v = q[lane] * qr[lane];
                    if (lane < 18) tile[c][r][lane] = v;
                    q += W; qr += W;
                }
            }
        } else {
#pragma unroll
            for (int k = 0; k < 2; k++) {
                int c = warp * 2 + k;
                int ch = ci0 + c;
                const float* q = hprev + ((size_t)b * Ch + ch) * HW
                                 + (size_t)(oy0 - 1) * W + (ox0 - 1);
#pragma unroll
                for (int r = 0; r < 18; r++) {
                    bool oky = (unsigned)(oy0 - 1 + r) < (unsigned)H;
                    float v = 0.f;
                    if (oky && okc) v = q[lane];
                    if (lane < 18) tile[c][r][lane] = v;
                    q += W;
                }
            }
        }
        for (int i = tid; i < CSTEP * 72; i += 128) {
            int c = i / 72, r = i % 72;
            int co = r / 9, kk = r % 9;
            ws[c][co][kk] = Wt[((size_t)(co0 + co) * CinTot + Cx + (ci0 + c)) * 9 + kk];
        }
        __syncthreads();

#pragma unroll
        for (int c = 0; c < CSTEP; c++) {
            float a[4][3];
#pragma unroll
            for (int i = 0; i < 4; i++)
#pragma unroll
                for (int j = 0; j < 3; j++)
                    a[i][j] = tile[c][2 * ty + i][tx + j];
#pragma unroll
            for (int co = 0; co < 8; co++) {
                float4 wa = *(const float4*)&ws[c][co][0];
                float4 wb = *(const float4*)&ws[c][co][4];
                float w8  = ws[c][co][8];
                acc0[co] += a[0][0]*wa.x + a[0][1]*wa.y + a[0][2]*wa.z
                          + a[1][0]*wa.w + a[1][1]*wb.x + a[1][2]*wb.y
                          + a[2][0]*wb.z + a[2][1]*wb.w + a[2][2]*w8;
                acc1[co] += a[1][0]*wa.x + a[1][1]*wa.y + a[1][2]*wa.z
                          + a[2][0]*wa.w + a[2][1]*wb.x + a[2][2]*wb.y
                          + a[3][0]*wb.z + a[3][1]*wb.w + a[3][2]*w8;
            }
        }
    }

    int oy = oy0 + 2 * ty, ox = ox0 + tx;
    if (mode == 0) {
#pragma unroll
        for (int co = 0; co < 8; co++) {
            size_t po = ((size_t)b * Cout + co0 + co) * HW + (size_t)oy * W + ox;
            float p0 = pre[po], p1 = pre[po + W];
            size_t o = (((size_t)b * Cout + co0 + co) * H + oy) * W + ox;
            out[o]     = sigf(acc0[co] + p0);
            out[o + W] = sigf(acc1[co] + p1);
        }
    } else {
#pragma unroll
        for (int co = 0; co < 8; co++) {
            int cc = co0 + co;
            size_t po = ((size_t)b * Cout + cc) * HW + (size_t)oy * W + ox;
            float p0 = pre[po], p1 = pre[po + W];
            size_t zo = (((size_t)b * 2 * Ch + Ch + cc) * H + oy) * W + ox;
            float z0 = gatesIn[zo], z1 = gatesIn[zo + W];
            size_t ho = (((size_t)b * Ch + cc) * H + oy) * W + ox;
            float h0v = hprev[ho], h1v = hprev[ho + W];
            out[ho]     = z0 * h0v + (1.f - z0) * ftanh(acc0[co] + p0);
            out[ho + W] = z1 * h1v + (1.f - z1) * ftanh(acc1[co] + p1);
        }
    }
}

// ---------------------------------------------------------------------------
// t = 0 step (h == 0): hn = (1 - sigmoid(z_pre)) * tanh(c_pre), elementwise.
// ---------------------------------------------------------------------------
__global__ void gru_t0(const float* __restrict__ gz, const float* __restrict__ gc,
                       float* __restrict__ hn, int Ch, int HW, int total)
{
    int i = blockIdx.x * 256 + threadIdx.x;
    if (i >= total) return;
    int b = i / (Ch * HW);
    float z = sigf(gz[(size_t)i + (size_t)(b + 1) * Ch * HW]);
    hn[i] = (1.f - z) * ftanh(gc[i]);
}

// ---------------------------------------------------------------------------
// Stride-2 3x3 conv (pad 1) + leaky relu(0.2), over all N = T*B samples.
// ---------------------------------------------------------------------------
__global__ void conv_s2_lrelu(const float* __restrict__ in, const float* __restrict__ Wt,
                              const float* __restrict__ bias, float* __restrict__ out,
                              int Cin, int Cout, int Hin, int Win, int sOuter, int sInner)
{
    int coutBlocks = Cout >> 3;
    int n  = blockIdx.x / coutBlocks;
    int cb = blockIdx.x % coutBlocks;
    int co0 = cb * 8;
    int t = n / 8, b = n % 8;
    const float* inN = in + (size_t)t * sOuter + (size_t)b * sInner;
    int Hout = Hin >> 1, Wout = Win >> 1;
    int oy0 = blockIdx.y * TS, ox0 = blockIdx.z * TS;
    int tx = threadIdx.x, ty = threadIdx.y;
    int tid = ty * 16 + tx;

    __shared__ float tile[CSTEP2][33][35];
    __shared__ float ws[CSTEP2][8][9];

    float acc0[8], acc1[8];
#pragma unroll
    for (int i = 0; i < 8; i++) { acc0[i] = 0.f; acc1[i] = 0.f; }

    for (int ci0 = 0; ci0 < Cin; ci0 += CSTEP2) {
        __syncthreads();
        for (int i = tid; i < CSTEP2 * 1089; i += 128) {
            int c = i / 1089, p = i % 1089;
            int ly = p / 33, lx = p % 33;
            int gy = 2 * oy0 - 1 + ly, gx = 2 * ox0 - 1 + lx;
            float v = 0.f;
            int ci = ci0 + c;
            if (ci < Cin && gy >= 0 && gy < Hin && gx >= 0 && gx < Win)
                v = inN[((size_t)ci * Hin + gy) * Win + gx];
            tile[c][ly][lx] = v;
        }
        for (int i = tid; i < CSTEP2 * 72; i += 128) {
            int c = i / 72, r = i % 72;
            int co = r / 9, k = r % 9;
            float wv = 0.f;
            if (ci0 + c < Cin)
                wv = Wt[((size_t)(co0 + co) * Cin + (ci0 + c)) * 9 + k];
            ws[c][co][k] = wv;
        }
        __syncthreads();

#pragma unroll
        for (int c = 0; c < CSTEP2; c++) {
            float a[5][3];
#pragma unroll
            for (int i = 0; i < 5; i++)
#pragma unroll
                for (int j = 0; j < 3; j++)
                    a[i][j] = tile[c][4 * ty + i][2 * tx + j];
#pragma unroll
            for (int co = 0; co < 8; co++) {
                float w0 = ws[c][co][0], w1 = ws[c][co][1], w2 = ws[c][co][2];
                float w3 = ws[c][co][3], w4 = ws[c][co][4], w5 = ws[c][co][5];
                float w6 = ws[c][co][6], w7 = ws[c][co][7], w8 = ws[c][co][8];
                acc0[co] += a[0][0]*w0 + a[0][1]*w1 + a[0][2]*w2
                          + a[1][0]*w3 + a[1][1]*w4 + a[1][2]*w5
                          + a[2][0]*w6 + a[2][1]*w7 + a[2][2]*w8;
                acc1[co] += a[2][0]*w0 + a[2][1]*w1 + a[2][2]*w2
                          + a[3][0]*w3 + a[3][1]*w4 + a[3][2]*w5
                          + a[4][0]*w6 + a[4][1]*w7 + a[4][2]*w8;
            }
        }
    }

    int oy = oy0 + 2 * ty, ox = ox0 + tx;
#pragma unroll
    for (int co = 0; co < 8; co++) {
        float bz = bias[co0 + co];
        float v0 = acc0[co] + bz, v1 = acc1[co] + bz;
        v0 = v0 > 0.f ? v0 : 0.2f * v0;
        v1 = v1 > 0.f ? v1 : 0.2f * v1;
        size_t o = (((size_t)n * Cout + co0 + co) * Hout + oy) * Wout + ox;
        out[o]        = v0;
        out[o + Wout] = v1;
    }
}

extern "C" void kernel_launch(void* const* d_in, const int* in_sizes, int n_in,
                              void* d_out, int out_size)
{
    const float* x   = (const float*)d_in[0];
    const float* W1  = (const float*)d_in[1];
    const float* b1  = (const float*)d_in[2];
    const float* Wg1 = (const float*)d_in[3];
    const float* bg1 = (const float*)d_in[4];
    const float* Wc1 = (const float*)d_in[5];
    const float* bc1 = (const float*)d_in[6];
    const float* W2  = (const float*)d_in[7];
    const float* b2  = (const float*)d_in[8];
    const float* Wg2 = (const float*)d_in[9];
    const float* bg2 = (const float*)d_in[10];
    const float* Wc2 = (const float*)d_in[11];
    const float* bc2 = (const float*)d_in[12];
    const float* W3  = (const float*)d_in[13];
    const float* b3  = (const float*)d_in[14];
    const float* Wg3 = (const float*)d_in[15];
    const float* bg3 = (const float*)d_in[16];
    const float* Wc3 = (const float*)d_in[17];
    const float* bc3 = (const float*)d_in[18];

    float* base = nullptr;
    cudaGetSymbolAddress((void**)&base, g_scratch);

    float* feat1 = base;                   // 10*8*16*64*64  = 5,242,880
    float* outs1 = base + 5242880;         // 10*8*64*64*64  = 20,971,520
    float* feat2 = base + 26214400;        // 10*8*64*32*32  = 5,242,880
    float* outs2 = base + 31457280;        // 10*8*96*32*32  = 7,864,320
    float* feat3 = base + 39321600;        // 10*8*96*16*16  = 1,966,080
    float* outs3 = base + 41287680;        // 10*8*96*16*16  = 1,966,080
    float* gates = base + 43253760;        // 8*192*64*64 max -> 4,194,304
    float* gxg1  = base + 47448064;        // 80*128*4096 = 41,943,040
    float* gxc1  = base + 89391104;        // 80*64*4096  = 20,971,520
    float* gxg2  = base + 110362624;       // 80*192*1024 = 15,728,640
    float* gxc2  = base + 126091264;       // 80*96*1024  =  7,864,320
    float* gxg3  = base + 133955584;       // 80*192*256  =  3,932,160
    float* gxc3  = base + 137887744;       // 80*96*256   =  1,966,080

    dim3 blk(16, 8);

    // ================= Stage 1 (H=W=64, Cx=16, Ch=64) =================
    conv_s2_lrelu<<<dim3(80 * 2, 4, 4), blk>>>(x, W1, b1, feat1,
                                               1, 16, 128, 128, 16384, 163840);
    conv_pre<<<dim3(80 * 16, 4, 4), blk>>>(feat1, Wg1, bg1, gxg1, 16, 80, 128, 64, 64);
    conv_pre<<<dim3(80 * 8, 4, 4), blk>>>(feat1, Wc1, bc1, gxc1, 16, 80, 64, 64, 64);
    gru_t0<<<(8 * 64 * 4096 + 255) / 256, 256>>>(gxg1, gxc1, outs1, 64, 4096, 8 * 64 * 4096);
    for (int t = 1; t < 10; t++) {
        const float* hp = outs1 + (size_t)(t - 1) * 8 * 64 * 4096;
        float* hn = outs1 + (size_t)t * 8 * 64 * 4096;
        gru_conv_h<<<dim3(8 * 16, 4, 4), blk>>>(hp, Wg1, gxg1 + (size_t)t * 8 * 128 * 4096,
                                                gates, gates, 16, 80, 64, 128, 64, 64, 0);
        gru_conv_h<<<dim3(8 * 8, 4, 4), blk>>>(hp, Wc1, gxc1 + (size_t)t * 8 * 64 * 4096,
                                               gates, hn, 16, 80, 64, 64, 64, 64, 1);
    }

    // ================= Stage 2 (H=W=32, Cx=64, Ch=96) =================
    conv_s2_lrelu<<<dim3(80 * 8, 2, 2), blk>>>(outs1, W2, b2, feat2,
                                               64, 64, 64, 64, 8 * 64 * 4096, 64 * 4096);
    conv_pre<<<dim3(80 * 24, 2, 2), blk>>>(feat2, Wg2, bg2, gxg2, 64, 160, 192, 32, 32);
    conv_pre<<<dim3(80 * 12, 2, 2), blk>>>(feat2, Wc2, bc2, gxc2, 64, 160, 96, 32, 32);
    gru_t0<<<(8 * 96 * 1024 + 255) / 256, 256>>>(gxg2, gxc2, outs2, 96, 1024, 8 * 96 * 1024);
    for (int t = 1; t < 10; t++) {
        const float* hp = outs2 + (size_t)(t - 1) * 8 * 96 * 1024;
        float* hn = outs2 + (size_t)t * 8 * 96 * 1024;
        gru_conv_h<<<dim3(8 * 24, 2, 2), blk>>>(hp, Wg2, gxg2 + (size_t)t * 8 * 192 * 1024,
                                                gates, gates, 64, 160, 96, 192, 32, 32, 0);
        gru_conv_h<<<dim3(8 * 12, 2, 2), blk>>>(hp, Wc2, gxc2 + (size_t)t * 8 * 96 * 1024,
                                                gates, hn, 64, 160, 96, 96, 32, 32, 1);
    }

    // ================= Stage 3 (H=W=16, Cx=96, Ch=96) =================
    conv_s2_lrelu<<<dim3(80 * 12, 1, 1), blk>>>(outs2, W3, b3, feat3,
                                                96, 96, 32, 32, 8 * 96 * 1024, 96 * 1024);
    conv_pre<<<dim3(80 * 24, 1, 1), blk>>>(feat3, Wg3, bg3, gxg3, 96, 192, 192, 16, 16);
    conv_pre<<<dim3(80 * 12, 1, 1), blk>>>(feat3, Wc3, bc3, gxc3, 96, 192, 96, 16, 16);
    gru_t0<<<(8 * 96 * 256 + 255) / 256, 256>>>(gxg3, gxc3, outs3, 96, 256, 8 * 96 * 256);
    for (int t = 1; t < 10; t++) {
        const float* hp = outs3 + (size_t)(t - 1) * 8 * 96 * 256;
        float* hn = outs3 + (size_t)t * 8 * 96 * 256;
        gru_conv_h<<<dim3(8 * 24, 1, 1), blk>>>(hp, Wg3, gxg3 + (size_t)t * 8 * 192 * 256,
                                                gates, gates, 96, 192, 96, 192, 16, 16, 0);
        gru_conv_h<<<dim3(8 * 12, 1, 1), blk>>>(hp, Wc3, gxc3 + (size_t)t * 8 * 96 * 256,
                                                gates, hn, 96, 192, 96, 96, 16, 16, 1);
    }

    // ---------------- Assemble output: (h1, h2, h3) flattened ----------------
    float* out = (float*)d_out;
    cudaMemcpyAsync(out,
                    outs1 + 9UL * 8 * 64 * 4096,
                    (size_t)8 * 64 * 4096 * sizeof(float),
                    cudaMemcpyDeviceToDevice, 0);
    cudaMemcpyAsync(out + 2097152,
                    outs2 + 9UL * 8 * 96 * 1024,
                    (size_t)8 * 96 * 1024 * sizeof(float),
                    cudaMemcpyDeviceToDevice, 0);
    cudaMemcpyAsync(out + 2097152 + 786432,
                    outs3 + 9UL * 8 * 96 * 256,
                    (size_t)8 * 96 * 256 * sizeof(float),
                    cudaMemcpyDeviceToDevice, 0);
}

// round 11
// speedup vs baseline: 1.8475x; 1.6287x over previous
#include <cuda_runtime.h>
#include <math.h>

#define TS 16
#define CSTEP 8
#define CSTEP2 4

// Scratch (fp32): feat/outs/gates + hoisted x-part conv results
__device__ float g_scratch[139853824];

__device__ __forceinline__ float sigf(float x) { return 1.f / (1.f + __expf(-x)); }
__device__ __forceinline__ float ftanh(float x) {
    float e = __expf(2.f * x);
    return 1.f - 2.f / (e + 1.f);
}

// ---------------------------------------------------------------------------
// Batched stride-1 3x3 conv (pad 1), raw output + bias. N samples contiguous.
// in: (N, Cin, H, W), weights OIHW row stride CinTot, out: (N, Cout, H, W).
// block (16,8), 8 couts/block. grid: (N * Cout/8, H/16, W/16)
// ---------------------------------------------------------------------------
__global__ __launch_bounds__(128)
void conv_pre(const float* __restrict__ in, const float* __restrict__ Wt,
              const float* __restrict__ bias, float* __restrict__ out,
              int Cin, int CinTot, int Cout, int H, int W)
{
    int coutBlocks = Cout >> 3;
    int n   = blockIdx.x / coutBlocks;
    int co0 = (blockIdx.x % coutBlocks) * 8;
    int oy0 = blockIdx.y * TS;
    int ox0 = blockIdx.z * TS;
    int tx = threadIdx.x, ty = threadIdx.y;
    int tid = ty * 16 + tx;

    __shared__ float tile[CSTEP][18][19];
    __shared__ __align__(16) float ws[CSTEP][8][12];

    int HW = H * W;
    const float* inN = in + (size_t)n * Cin * HW;

    // incremental loader initial state (tid < 324 -> starts in channel 0)
    const int iy00 = tid / 18, ix00 = tid % 18;

    float acc0[8], acc1[8];
#pragma unroll
    for (int i = 0; i < 8; i++) { acc0[i] = 0.f; acc1[i] = 0.f; }

    for (int ci0 = 0; ci0 < Cin; ci0 += CSTEP) {
        __syncthreads();
        // strided loader, incremental index arithmetic (same addresses/order
        // as the div/mod version; i advances by 128 over 8*324 elements)
        {
            const float* src = inN + (size_t)ci0 * HW;
            int iy = iy00, ix = ix00;
            int gy = oy0 - 1 + iy, gx = ox0 - 1 + ix;
            int sof = iy * 19 + ix;
            int goff = gy * W + gx;
            for (int i = tid; i < CSTEP * 324; i += 128) {
                float v = 0.f;
                if ((unsigned)gy < (unsigned)H && (unsigned)gx < (unsigned)W)
                    v = src[goff];
                ((float*)tile)[sof] = v;
                ix += 2; iy += 7; gy += 7; gx += 2;
                goff += 7 * W + 2; sof += 135;
                if (ix >= 18) { ix -= 18; gx -= 18; iy += 1; gy += 1;
                                goff += W - 18; sof += 1; }
                if (iy >= 18) { iy -= 18; gy -= 18; goff += HW - 18 * W; }
            }
        }
        for (int i = tid; i < CSTEP * 72; i += 128) {
            int c = i / 72, r = i % 72;
            int co = r / 9, kk = r % 9;
            ws[c][co][kk] = Wt[((size_t)(co0 + co) * CinTot + (ci0 + c)) * 9 + kk];
        }
        __syncthreads();

#pragma unroll
        for (int c = 0; c < CSTEP; c++) {
            float a[4][3];
#pragma unroll
            for (int i = 0; i < 4; i++)
#pragma unroll
                for (int j = 0; j < 3; j++)
                    a[i][j] = tile[c][2 * ty + i][tx + j];
#pragma unroll
            for (int co = 0; co < 8; co++) {
                float4 wa = *(const float4*)&ws[c][co][0];
                float4 wb = *(const float4*)&ws[c][co][4];
                float w8  = ws[c][co][8];
                acc0[co] += a[0][0]*wa.x + a[0][1]*wa.y + a[0][2]*wa.z
                          + a[1][0]*wa.w + a[1][1]*wb.x + a[1][2]*wb.y
                          + a[2][0]*wb.z + a[2][1]*wb.w + a[2][2]*w8;
                acc1[co] += a[1][0]*wa.x + a[1][1]*wa.y + a[1][2]*wa.z
                          + a[2][0]*wa.w + a[2][1]*wb.x + a[2][2]*wb.y
                          + a[3][0]*wb.z + a[3][1]*wb.w + a[3][2]*w8;
            }
        }
    }

    int oy = oy0 + 2 * ty, ox = ox0 + tx;
#pragma unroll
    for (int co = 0; co < 8; co++) {
        float bz = bias[co0 + co];
        size_t o = ((size_t)n * Cout + co0 + co) * HW + (size_t)oy * W + ox;
        out[o]     = acc0[co] + bz;
        out[o + W] = acc1[co] + bz;
    }
}

// ---------------------------------------------------------------------------
// Recurrent h-part conv (t >= 1). Conv over Ch channels of hprev (mode 1:
// multiplied by r from gatesIn), seeded by pre (= bias + x-part).
// mode 0: gates -> sigmoid.  mode 1: cand -> GRU update.
// grid: (B * Cout/8, H/16, W/16)
// ---------------------------------------------------------------------------
__global__ __launch_bounds__(128)
void gru_conv_h(const float* __restrict__ hprev, const float* __restrict__ Wt,
                const float* __restrict__ pre, const float* __restrict__ gatesIn,
                float* __restrict__ out,
                int Cx, int CinTot, int Ch, int Cout, int H, int W, int mode)
{
    int coutBlocks = Cout >> 3;
    int b   = blockIdx.x / coutBlocks;
    int co0 = (blockIdx.x % coutBlocks) * 8;
    int oy0 = blockIdx.y * TS;
    int ox0 = blockIdx.z * TS;
    int tx = threadIdx.x, ty = threadIdx.y;
    int tid = ty * 16 + tx;

    __shared__ float tile[CSTEP][18][19];
    __shared__ __align__(16) float ws[CSTEP][8][12];

    int HW = H * W;
    const int iy00 = tid / 18, ix00 = tid % 18;

    float acc0[8], acc1[8];
#pragma unroll
    for (int i = 0; i < 8; i++) { acc0[i] = 0.f; acc1[i] = 0.f; }

    for (int ci0 = 0; ci0 < Ch; ci0 += CSTEP) {
        __syncthreads();
        // strided loader, incremental index arithmetic
        {
            const float* hs = hprev + ((size_t)b * Ch + ci0) * HW;
            const float* rs = gatesIn + ((size_t)b * 2 * Ch + ci0) * HW;
            int iy = iy00, ix = ix00;
            int gy = oy0 - 1 + iy, gx = ox0 - 1 + ix;
            int sof = iy * 19 + ix;
            int goff = gy * W + gx;
            if (mode) {
                for (int i = tid; i < CSTEP * 324; i += 128) {
                    float v = 0.f;
                    if ((unsigned)gy < (unsigned)H && (unsigned)gx < (unsigned)W)
                        v = hs[goff] * rs[goff];
                    ((float*)tile)[sof] = v;
                    ix += 2; iy += 7; gy += 7; gx += 2;
                    goff += 7 * W + 2; sof += 135;
                    if (ix >= 18) { ix -= 18; gx -= 18; iy += 1; gy += 1;
                                    goff += W - 18; sof += 1; }
                    if (iy >= 18) { iy -= 18; gy -= 18; goff += HW - 18 * W; }
                }
            } else {
                for (int i = tid; i < CSTEP * 324; i += 128) {
                    float v = 0.f;
                    if ((unsigned)gy < (unsigned)H && (unsigned)gx < (unsigned)W)
                        v = hs[goff];
                    ((float*)tile)[sof] = v;
                    ix += 2; iy += 7; gy += 7; gx += 2;
                    goff += 7 * W + 2; sof += 135;
                    if (ix >= 18) { ix -= 18; gx -= 18; iy += 1; gy += 1;
                                    goff += W - 18; sof += 1; }
                    if (iy >= 18) { iy -= 18; gy -= 18; goff += HW - 18 * W; }
                }
            }
        }
        for (int i = tid; i < CSTEP * 72; i += 128) {
            int c = i / 72, r = i % 72;
            int co = r / 9, kk = r % 9;
            ws[c][co][kk] = Wt[((size_t)(co0 + co) * CinTot + Cx + (ci0 + c)) * 9 + kk];
        }
        __syncthreads();

#pragma unroll
        for (int c = 0; c < CSTEP; c++) {
            float a[4][3];
#pragma unroll
            for (int i = 0; i < 4; i++)
#pragma unroll
                for (int j = 0; j < 3; j++)
                    a[i][j] = tile[c][2 * ty + i][tx + j];
#pragma unroll
            for (int co = 0; co < 8; co++) {
                float4 wa = *(const float4*)&ws[c][co][0];
                float4 wb = *(const float4*)&ws[c][co][4];
                float w8  = ws[c][co][8];
                acc0[co] += a[0][0]*wa.x + a[0][1]*wa.y + a[0][2]*wa.z
                          + a[1][0]*wa.w + a[1][1]*wb.x + a[1][2]*wb.y
                          + a[2][0]*wb.z + a[2][1]*wb.w + a[2][2]*w8;
                acc1[co] += a[1][0]*wa.x + a[1][1]*wa.y + a[1][2]*wa.z
                          + a[2][0]*wa.w + a[2][1]*wb.x + a[2][2]*wb.y
                          + a[3][0]*wb.z + a[3][1]*wb.w + a[3][2]*w8;
            }
        }
    }

    int oy = oy0 + 2 * ty, ox = ox0 + tx;
    if (mode == 0) {
#pragma unroll
        for (int co = 0; co < 8; co++) {
            size_t po = ((size_t)b * Cout + co0 + co) * HW + (size_t)oy * W + ox;
            float p0 = pre[po], p1 = pre[po + W];
            size_t o = (((size_t)b * Cout + co0 + co) * H + oy) * W + ox;
            out[o]     = sigf(acc0[co] + p0);
            out[o + W] = sigf(acc1[co] + p1);
        }
    } else {
#pragma unroll
        for (int co = 0; co < 8; co++) {
            int cc = co0 + co;
            size_t po = ((size_t)b * Cout + cc) * HW + (size_t)oy * W + ox;
            float p0 = pre[po], p1 = pre[po + W];
            size_t zo = (((size_t)b * 2 * Ch + Ch + cc) * H + oy) * W + ox;
            float z0 = gatesIn[zo], z1 = gatesIn[zo + W];
            size_t ho = (((size_t)b * Ch + cc) * H + oy) * W + ox;
            float h0v = hprev[ho], h1v = hprev[ho + W];
            out[ho]     = z0 * h0v + (1.f - z0) * ftanh(acc0[co] + p0);
            out[ho + W] = z1 * h1v + (1.f - z1) * ftanh(acc1[co] + p1);
        }
    }
}

// ---------------------------------------------------------------------------
// t = 0 step (h == 0): hn = (1 - sigmoid(z_pre)) * tanh(c_pre), elementwise.
// ---------------------------------------------------------------------------
__global__ void gru_t0(const float* __restrict__ gz, const float* __restrict__ gc,
                       float* __restrict__ hn, int Ch, int HW, int total)
{
    int i = blockIdx.x * 256 + threadIdx.x;
    if (i >= total) return;
    int b = i / (Ch * HW);
    float z = sigf(gz[(size_t)i + (size_t)(b + 1) * Ch * HW]);
    hn[i] = (1.f - z) * ftanh(gc[i]);
}

// ---------------------------------------------------------------------------
// Stride-2 3x3 conv (pad 1) + leaky relu(0.2), over all N = T*B samples.
// ---------------------------------------------------------------------------
__global__ void conv_s2_lrelu(const float* __restrict__ in, const float* __restrict__ Wt,
                              const float* __restrict__ bias, float* __restrict__ out,
                              int Cin, int Cout, int Hin, int Win, int sOuter, int sInner)
{
    int coutBlocks = Cout >> 3;
    int n  = blockIdx.x / coutBlocks;
    int cb = blockIdx.x % coutBlocks;
    int co0 = cb * 8;
    int t = n / 8, b = n % 8;
    const float* inN = in + (size_t)t * sOuter + (size_t)b * sInner;
    int Hout = Hin >> 1, Wout = Win >> 1;
    int oy0 = blockIdx.y * TS, ox0 = blockIdx.z * TS;
    int tx = threadIdx.x, ty = threadIdx.y;
    int tid = ty * 16 + tx;

    __shared__ float tile[CSTEP2][33][35];
    __shared__ float ws[CSTEP2][8][9];

    float acc0[8], acc1[8];
#pragma unroll
    for (int i = 0; i < 8; i++) { acc0[i] = 0.f; acc1[i] = 0.f; }

    for (int ci0 = 0; ci0 < Cin; ci0 += CSTEP2) {
        __syncthreads();
        for (int i = tid; i < CSTEP2 * 1089; i += 128) {
            int c = i / 1089, p = i % 1089;
            int ly = p / 33, lx = p % 33;
            int gy = 2 * oy0 - 1 + ly, gx = 2 * ox0 - 1 + lx;
            float v = 0.f;
            int ci = ci0 + c;
            if (ci < Cin && gy >= 0 && gy < Hin && gx >= 0 && gx < Win)
                v = inN[((size_t)ci * Hin + gy) * Win + gx];
            tile[c][ly][lx] = v;
        }
        for (int i = tid; i < CSTEP2 * 72; i += 128) {
            int c = i / 72, r = i % 72;
            int co = r / 9, k = r % 9;
            float wv = 0.f;
            if (ci0 + c < Cin)
                wv = Wt[((size_t)(co0 + co) * Cin + (ci0 + c)) * 9 + k];
            ws[c][co][k] = wv;
        }
        __syncthreads();

#pragma unroll
        for (int c = 0; c < CSTEP2; c++) {
            float a[5][3];
#pragma unroll
            for (int i = 0; i < 5; i++)
#pragma unroll
                for (int j = 0; j < 3; j++)
                    a[i][j] = tile[c][4 * ty + i][2 * tx + j];
#pragma unroll
            for (int co = 0; co < 8; co++) {
                float w0 = ws[c][co][0], w1 = ws[c][co][1], w2 = ws[c][co][2];
                float w3 = ws[c][co][3], w4 = ws[c][co][4], w5 = ws[c][co][5];
                float w6 = ws[c][co][6], w7 = ws[c][co][7], w8 = ws[c][co][8];
                acc0[co] += a[0][0]*w0 + a[0][1]*w1 + a[0][2]*w2
                          + a[1][0]*w3 + a[1][1]*w4 + a[1][2]*w5
                          + a[2][0]*w6 + a[2][1]*w7 + a[2][2]*w8;
                acc1[co] += a[2][0]*w0 + a[2][1]*w1 + a[2][2]*w2
                          + a[3][0]*w3 + a[3][1]*w4 + a[3][2]*w5
                          + a[4][0]*w6 + a[4][1]*w7 + a[4][2]*w8;
            }
        }
    }

    int oy = oy0 + 2 * ty, ox = ox0 + tx;
#pragma unroll
    for (int co = 0; co < 8; co++) {
        float bz = bias[co0 + co];
        float v0 = acc0[co] + bz, v1 = acc1[co] + bz;
        v0 = v0 > 0.f ? v0 : 0.2f * v0;
        v1 = v1 > 0.f ? v1 : 0.2f * v1;
        size_t o = (((size_t)n * Cout + co0 + co) * Hout + oy) * Wout + ox;
        out[o]        = v0;
        out[o + Wout] = v1;
    }
}

extern "C" void kernel_launch(void* const* d_in, const int* in_sizes, int n_in,
                              void* d_out, int out_size)
{
    const float* x   = (const float*)d_in[0];
    const float* W1  = (const float*)d_in[1];
    const float* b1  = (const float*)d_in[2];
    const float* Wg1 = (const float*)d_in[3];
    const float* bg1 = (const float*)d_in[4];
    const float* Wc1 = (const float*)d_in[5];
    const float* bc1 = (const float*)d_in[6];
    const float* W2  = (const float*)d_in[7];
    const float* b2  = (const float*)d_in[8];
    const float* Wg2 = (const float*)d_in[9];
    const float* bg2 = (const float*)d_in[10];
    const float* Wc2 = (const float*)d_in[11];
    const float* bc2 = (const float*)d_in[12];
    const float* W3  = (const float*)d_in[13];
    const float* b3  = (const float*)d_in[14];
    const float* Wg3 = (const float*)d_in[15];
    const float* bg3 = (const float*)d_in[16];
    const float* Wc3 = (const float*)d_in[17];
    const float* bc3 = (const float*)d_in[18];

    float* base = nullptr;
    cudaGetSymbolAddress((void**)&base, g_scratch);

    float* feat1 = base;                   // 10*8*16*64*64  = 5,242,880
    float* outs1 = base + 5242880;         // 10*8*64*64*64  = 20,971,520
    float* feat2 = base + 26214400;        // 10*8*64*32*32  = 5,242,880
    float* outs2 = base + 31457280;        // 10*8*96*32*32  = 7,864,320
    float* feat3 = base + 39321600;        // 10*8*96*16*16  = 1,966,080
    float* outs3 = base + 41287680;        // 10*8*96*16*16  = 1,966,080
    float* gates = base + 43253760;        // 8*192*64*64 max -> 4,194,304
    float* gxg1  = base + 47448064;        // 80*128*4096 = 41,943,040
    float* gxc1  = base + 89391104;        // 80*64*4096  = 20,971,520
    float* gxg2  = base + 110362624;       // 80*192*1024 = 15,728,640
    float* gxc2  = base + 126091264;       // 80*96*1024  =  7,864,320
    float* gxg3  = base + 133955584;       // 80*192*256  =  3,932,160
    float* gxc3  = base + 137887744;       // 80*96*256   =  1,966,080

    dim3 blk(16, 8);

    // ================= Stage 1 (H=W=64, Cx=16, Ch=64) =================
    conv_s2_lrelu<<<dim3(80 * 2, 4, 4), blk>>>(x, W1, b1, feat1,
                                               1, 16, 128, 128, 16384, 163840);
    conv_pre<<<dim3(80 * 16, 4, 4), blk>>>(feat1, Wg1, bg1, gxg1, 16, 80, 128, 64, 64);
    conv_pre<<<dim3(80 * 8, 4, 4), blk>>>(feat1, Wc1, bc1, gxc1, 16, 80, 64, 64, 64);
    gru_t0<<<(8 * 64 * 4096 + 255) / 256, 256>>>(gxg1, gxc1, outs1, 64, 4096, 8 * 64 * 4096);
    for (int t = 1; t < 10; t++) {
        const float* hp = outs1 + (size_t)(t - 1) * 8 * 64 * 4096;
        float* hn = outs1 + (size_t)t * 8 * 64 * 4096;
        gru_conv_h<<<dim3(8 * 16, 4, 4), blk>>>(hp, Wg1, gxg1 + (size_t)t * 8 * 128 * 4096,
                                                gates, gates, 16, 80, 64, 128, 64, 64, 0);
        gru_conv_h<<<dim3(8 * 8, 4, 4), blk>>>(hp, Wc1, gxc1 + (size_t)t * 8 * 64 * 4096,
                                               gates, hn, 16, 80, 64, 64, 64, 64, 1);
    }

    // ================= Stage 2 (H=W=32, Cx=64, Ch=96) =================
    conv_s2_lrelu<<<dim3(80 * 8, 2, 2), blk>>>(outs1, W2, b2, feat2,
                                               64, 64, 64, 64, 8 * 64 * 4096, 64 * 4096);
    conv_pre<<<dim3(80 * 24, 2, 2), blk>>>(feat2, Wg2, bg2, gxg2, 64, 160, 192, 32, 32);
    conv_pre<<<dim3(80 * 12, 2, 2), blk>>>(feat2, Wc2, bc2, gxc2, 64, 160, 96, 32, 32);
    gru_t0<<<(8 * 96 * 1024 + 255) / 256, 256>>>(gxg2, gxc2, outs2, 96, 1024, 8 * 96 * 1024);
    for (int t = 1; t < 10; t++) {
        const float* hp = outs2 + (size_t)(t - 1) * 8 * 96 * 1024;
        float* hn = outs2 + (size_t)t * 8 * 96 * 1024;
        gru_conv_h<<<dim3(8 * 24, 2, 2), blk>>>(hp, Wg2, gxg2 + (size_t)t * 8 * 192 * 1024,
                                                gates, gates, 64, 160, 96, 192, 32, 32, 0);
        gru_conv_h<<<dim3(8 * 12, 2, 2), blk>>>(hp, Wc2, gxc2 + (size_t)t * 8 * 96 * 1024,
                                                gates, hn, 64, 160, 96, 96, 32, 32, 1);
    }

    // ================= Stage 3 (H=W=16, Cx=96, Ch=96) =================
    conv_s2_lrelu<<<dim3(80 * 12, 1, 1), blk>>>(outs2, W3, b3, feat3,
                                                96, 96, 32, 32, 8 * 96 * 1024, 96 * 1024);
    conv_pre<<<dim3(80 * 24, 1, 1), blk>>>(feat3, Wg3, bg3, gxg3, 96, 192, 192, 16, 16);
    conv_pre<<<dim3(80 * 12, 1, 1), blk>>>(feat3, Wc3, bc3, gxc3, 96, 192, 96, 16, 16);
    gru_t0<<<(8 * 96 * 256 + 255) / 256, 256>>>(gxg3, gxc3, outs3, 96, 256, 8 * 96 * 256);
    for (int t = 1; t < 10; t++) {
        const float* hp = outs3 + (size_t)(t - 1) * 8 * 96 * 256;
        float* hn = outs3 + (size_t)t * 8 * 96 * 256;
        gru_conv_h<<<dim3(8 * 24, 1, 1), blk>>>(hp, Wg3, gxg3 + (size_t)t * 8 * 192 * 256,
                                                gates, gates, 96, 192, 96, 192, 16, 16, 0);
        gru_conv_h<<<dim3(8 * 12, 1, 1), blk>>>(hp, Wc3, gxc3 + (size_t)t * 8 * 96 * 256,
                                                gates, hn, 96, 192, 96, 96, 16, 16, 1);
    }

    // ---------------- Assemble output: (h1, h2, h3) flattened ----------------
    float* out = (float*)d_out;
    cudaMemcpyAsync(out,
                    outs1 + 9UL * 8 * 64 * 4096,
                    (size_t)8 * 64 * 4096 * sizeof(float),
                    cudaMemcpyDeviceToDevice, 0);
    cudaMemcpyAsync(out + 2097152,
                    outs2 + 9UL * 8 * 96 * 1024,
                    (size_t)8 * 96 * 1024 * sizeof(float),
                    cudaMemcpyDeviceToDevice, 0);
    cudaMemcpyAsync(out + 2097152 + 786432,
                    outs3 + 9UL * 8 * 96 * 256,
                    (size_t)8 * 96 * 256 * sizeof(float),
                    cudaMemcpyDeviceToDevice, 0);
}

// round 12
// speedup vs baseline: 2.0262x; 1.0967x over previous
#include <cuda_runtime.h>
#include <math.h>

#define TS 16
#define CSTEP 8
#define CSTEP2 4

// Scratch (fp32): feat/outs/gates + hoisted x-part conv results
__device__ float g_scratch[141819904];

__device__ __forceinline__ float sigf(float x) { return 1.f / (1.f + __expf(-x)); }
__device__ __forceinline__ float ftanh(float x) {
    float e = __expf(2.f * x);
    return 1.f - 2.f / (e + 1.f);
}

// ---------------------------------------------------------------------------
// Batched stride-1 3x3 conv (pad 1), raw output + bias. N samples contiguous.
// in: (N, Cin, H, W), weights OIHW row stride CinTot, out: (N, Cout, H, W).
// block (16,8), 8 couts/block. grid: (N * Cout/8, H/16, W/16)
// ---------------------------------------------------------------------------
__global__ __launch_bounds__(128)
void conv_pre(const float* __restrict__ in, const float* __restrict__ Wt,
              const float* __restrict__ bias, float* __restrict__ out,
              int Cin, int CinTot, int Cout, int H, int W)
{
    int coutBlocks = Cout >> 3;
    int n   = blockIdx.x / coutBlocks;
    int co0 = (blockIdx.x % coutBlocks) * 8;
    int oy0 = blockIdx.y * TS;
    int ox0 = blockIdx.z * TS;
    int tx = threadIdx.x, ty = threadIdx.y;
    int tid = ty * 16 + tx;

    __shared__ float tile[CSTEP][18][19];
    __shared__ __align__(16) float ws[CSTEP][8][12];

    int HW = H * W;
    const float* inN = in + (size_t)n * Cin * HW;

    const int iy00 = tid / 18, ix00 = tid % 18;

    float acc0[8], acc1[8];
#pragma unroll
    for (int i = 0; i < 8; i++) { acc0[i] = 0.f; acc1[i] = 0.f; }

    for (int ci0 = 0; ci0 < Cin; ci0 += CSTEP) {
        __syncthreads();
        {
            const float* src = inN + (size_t)ci0 * HW;
            int iy = iy00, ix = ix00;
            int gy = oy0 - 1 + iy, gx = ox0 - 1 + ix;
            int sof = iy * 19 + ix;
            int goff = gy * W + gx;
            for (int i = tid; i < CSTEP * 324; i += 128) {
                float v = 0.f;
                if ((unsigned)gy < (unsigned)H && (unsigned)gx < (unsigned)W)
                    v = src[goff];
                ((float*)tile)[sof] = v;
                ix += 2; iy += 7; gy += 7; gx += 2;
                goff += 7 * W + 2; sof += 135;
                if (ix >= 18) { ix -= 18; gx -= 18; iy += 1; gy += 1;
                                goff += W - 18; sof += 1; }
                if (iy >= 18) { iy -= 18; gy -= 18; goff += HW - 18 * W; }
            }
        }
        for (int i = tid; i < CSTEP * 72; i += 128) {
            int c = i / 72, r = i % 72;
            int co = r / 9, kk = r % 9;
            ws[c][co][kk] = Wt[((size_t)(co0 + co) * CinTot + (ci0 + c)) * 9 + kk];
        }
        __syncthreads();

#pragma unroll
        for (int c = 0; c < CSTEP; c++) {
            float a[4][3];
#pragma unroll
            for (int i = 0; i < 4; i++)
#pragma unroll
                for (int j = 0; j < 3; j++)
                    a[i][j] = tile[c][2 * ty + i][tx + j];
#pragma unroll
            for (int co = 0; co < 8; co++) {
                float4 wa = *(const float4*)&ws[c][co][0];
                float4 wb = *(const float4*)&ws[c][co][4];
                float w8  = ws[c][co][8];
                acc0[co] += a[0][0]*wa.x + a[0][1]*wa.y + a[0][2]*wa.z
                          + a[1][0]*wa.w + a[1][1]*wb.x + a[1][2]*wb.y
                          + a[2][0]*wb.z + a[2][1]*wb.w + a[2][2]*w8;
                acc1[co] += a[1][0]*wa.x + a[1][1]*wa.y + a[1][2]*wa.z
                          + a[2][0]*wa.w + a[2][1]*wb.x + a[2][2]*wb.y
                          + a[3][0]*wb.z + a[3][1]*wb.w + a[3][2]*w8;
            }
        }
    }

    int oy = oy0 + 2 * ty, ox = ox0 + tx;
#pragma unroll
    for (int co = 0; co < 8; co++) {
        float bz = bias[co0 + co];
        size_t o = ((size_t)n * Cout + co0 + co) * HW + (size_t)oy * W + ox;
        out[o]     = acc0[co] + bz;
        out[o + W] = acc1[co] + bz;
    }
}

// ---------------------------------------------------------------------------
// Recurrent h-part conv (t >= 1). mode 0: gates -> sigmoid. mode 1: cand ->
// GRU update. Seeded by pre (= bias + x-part). grid: (B*Cout/8, H/16, W/16)
// ---------------------------------------------------------------------------
__global__ __launch_bounds__(128)
void gru_conv_h(const float* __restrict__ hprev, const float* __restrict__ Wt,
                const float* __restrict__ pre, const float* __restrict__ gatesIn,
                float* __restrict__ out,
                int Cx, int CinTot, int Ch, int Cout, int H, int W, int mode)
{
    int coutBlocks = Cout >> 3;
    int b   = blockIdx.x / coutBlocks;
    int co0 = (blockIdx.x % coutBlocks) * 8;
    int oy0 = blockIdx.y * TS;
    int ox0 = blockIdx.z * TS;
    int tx = threadIdx.x, ty = threadIdx.y;
    int tid = ty * 16 + tx;

    __shared__ float tile[CSTEP][18][19];
    __shared__ __align__(16) float ws[CSTEP][8][12];

    int HW = H * W;
    const int iy00 = tid / 18, ix00 = tid % 18;

    float acc0[8], acc1[8];
#pragma unroll
    for (int i = 0; i < 8; i++) { acc0[i] = 0.f; acc1[i] = 0.f; }

    for (int ci0 = 0; ci0 < Ch; ci0 += CSTEP) {
        __syncthreads();
        {
            const float* hs = hprev + ((size_t)b * Ch + ci0) * HW;
            const float* rs = gatesIn + ((size_t)b * 2 * Ch + ci0) * HW;
            int iy = iy00, ix = ix00;
            int gy = oy0 - 1 + iy, gx = ox0 - 1 + ix;
            int sof = iy * 19 + ix;
            int goff = gy * W + gx;
            if (mode) {
                for (int i = tid; i < CSTEP * 324; i += 128) {
                    float v = 0.f;
                    if ((unsigned)gy < (unsigned)H && (unsigned)gx < (unsigned)W)
                        v = hs[goff] * rs[goff];
                    ((float*)tile)[sof] = v;
                    ix += 2; iy += 7; gy += 7; gx += 2;
                    goff += 7 * W + 2; sof += 135;
                    if (ix >= 18) { ix -= 18; gx -= 18; iy += 1; gy += 1;
                                    goff += W - 18; sof += 1; }
                    if (iy >= 18) { iy -= 18; gy -= 18; goff += HW - 18 * W; }
                }
            } else {
                for (int i = tid; i < CSTEP * 324; i += 128) {
                    float v = 0.f;
                    if ((unsigned)gy < (unsigned)H && (unsigned)gx < (unsigned)W)
                        v = hs[goff];
                    ((float*)tile)[sof] = v;
                    ix += 2; iy += 7; gy += 7; gx += 2;
                    goff += 7 * W + 2; sof += 135;
                    if (ix >= 18) { ix -= 18; gx -= 18; iy += 1; gy += 1;
                                    goff += W - 18; sof += 1; }
                    if (iy >= 18) { iy -= 18; gy -= 18; goff += HW - 18 * W; }
                }
            }
        }
        for (int i = tid; i < CSTEP * 72; i += 128) {
            int c = i / 72, r = i % 72;
            int co = r / 9, kk = r % 9;
            ws[c][co][kk] = Wt[((size_t)(co0 + co) * CinTot + Cx + (ci0 + c)) * 9 + kk];
        }
        __syncthreads();

#pragma unroll
        for (int c = 0; c < CSTEP; c++) {
            float a[4][3];
#pragma unroll
            for (int i = 0; i < 4; i++)
#pragma unroll
                for (int j = 0; j < 3; j++)
                    a[i][j] = tile[c][2 * ty + i][tx + j];
#pragma unroll
            for (int co = 0; co < 8; co++) {
                float4 wa = *(const float4*)&ws[c][co][0];
                float4 wb = *(const float4*)&ws[c][co][4];
                float w8  = ws[c][co][8];
                acc0[co] += a[0][0]*wa.x + a[0][1]*wa.y + a[0][2]*wa.z
                          + a[1][0]*wa.w + a[1][1]*wb.x + a[1][2]*wb.y
                          + a[2][0]*wb.z + a[2][1]*wb.w + a[2][2]*w8;
                acc1[co] += a[1][0]*wa.x + a[1][1]*wa.y + a[1][2]*wa.z
                          + a[2][0]*wa.w + a[2][1]*wb.x + a[2][2]*wb.y
                          + a[3][0]*wb.z + a[3][1]*wb.w + a[3][2]*w8;
            }
        }
    }

    int oy = oy0 + 2 * ty, ox = ox0 + tx;
    if (mode == 0) {
#pragma unroll
        for (int co = 0; co < 8; co++) {
            size_t po = ((size_t)b * Cout + co0 + co) * HW + (size_t)oy * W + ox;
            float p0 = pre[po], p1 = pre[po + W];
            size_t o = (((size_t)b * Cout + co0 + co) * H + oy) * W + ox;
            out[o]     = sigf(acc0[co] + p0);
            out[o + W] = sigf(acc1[co] + p1);
        }
    } else {
#pragma unroll
        for (int co = 0; co < 8; co++) {
            int cc = co0 + co;
            size_t po = ((size_t)b * Cout + cc) * HW + (size_t)oy * W + ox;
            float p0 = pre[po], p1 = pre[po + W];
            size_t zo = (((size_t)b * 2 * Ch + Ch + cc) * H + oy) * W + ox;
            float z0 = gatesIn[zo], z1 = gatesIn[zo + W];
            size_t ho = (((size_t)b * Ch + cc) * H + oy) * W + ox;
            float h0v = hprev[ho], h1v = hprev[ho + W];
            out[ho]     = z0 * h0v + (1.f - z0) * ftanh(acc0[co] + p0);
            out[ho + W] = z1 * h1v + (1.f - z1) * ftanh(acc1[co] + p1);
        }
    }
}

// ---------------------------------------------------------------------------
// t = 0 step (h == 0): hn = (1 - sigmoid(z_pre)) * tanh(c_pre), elementwise.
// ---------------------------------------------------------------------------
__global__ void gru_t0(const float* __restrict__ gz, const float* __restrict__ gc,
                       float* __restrict__ hn, int Ch, int HW, int total)
{
    int i = blockIdx.x * 256 + threadIdx.x;
    if (i >= total) return;
    int b = i / (Ch * HW);
    float z = sigf(gz[(size_t)i + (size_t)(b + 1) * Ch * HW]);
    hn[i] = (1.f - z) * ftanh(gc[i]);
}

// ---------------------------------------------------------------------------
// Stride-2 3x3 conv (pad 1) + leaky relu(0.2), N = gridDim.x/coutBlocks samples.
// ---------------------------------------------------------------------------
__global__ void conv_s2_lrelu(const float* __restrict__ in, const float* __restrict__ Wt,
                              const float* __restrict__ bias, float* __restrict__ out,
                              int Cin, int Cout, int Hin, int Win, int sOuter, int sInner)
{
    int coutBlocks = Cout >> 3;
    int n  = blockIdx.x / coutBlocks;
    int cb = blockIdx.x % coutBlocks;
    int co0 = cb * 8;
    int t = n / 8, b = n % 8;
    const float* inN = in + (size_t)t * sOuter + (size_t)b * sInner;
    int Hout = Hin >> 1, Wout = Win >> 1;
    int oy0 = blockIdx.y * TS, ox0 = blockIdx.z * TS;
    int tx = threadIdx.x, ty = threadIdx.y;
    int tid = ty * 16 + tx;

    __shared__ float tile[CSTEP2][33][35];
    __shared__ float ws[CSTEP2][8][9];

    float acc0[8], acc1[8];
#pragma unroll
    for (int i = 0; i < 8; i++) { acc0[i] = 0.f; acc1[i] = 0.f; }

    for (int ci0 = 0; ci0 < Cin; ci0 += CSTEP2) {
        __syncthreads();
        for (int i = tid; i < CSTEP2 * 1089; i += 128) {
            int c = i / 1089, p = i % 1089;
            int ly = p / 33, lx = p % 33;
            int gy = 2 * oy0 - 1 + ly, gx = 2 * ox0 - 1 + lx;
            float v = 0.f;
            int ci = ci0 + c;
            if (ci < Cin && gy >= 0 && gy < Hin && gx >= 0 && gx < Win)
                v = inN[((size_t)ci * Hin + gy) * Win + gx];
            tile[c][ly][lx] = v;
        }
        for (int i = tid; i < CSTEP2 * 72; i += 128) {
            int c = i / 72, r = i % 72;
            int co = r / 9, k = r % 9;
            float wv = 0.f;
            if (ci0 + c < Cin)
                wv = Wt[((size_t)(co0 + co) * Cin + (ci0 + c)) * 9 + k];
            ws[c][co][k] = wv;
        }
        __syncthreads();

#pragma unroll
        for (int c = 0; c < CSTEP2; c++) {
            float a[5][3];
#pragma unroll
            for (int i = 0; i < 5; i++)
#pragma unroll
                for (int j = 0; j < 3; j++)
                    a[i][j] = tile[c][4 * ty + i][2 * tx + j];
#pragma unroll
            for (int co = 0; co < 8; co++) {
                float w0 = ws[c][co][0], w1 = ws[c][co][1], w2 = ws[c][co][2];
                float w3 = ws[c][co][3], w4 = ws[c][co][4], w5 = ws[c][co][5];
                float w6 = ws[c][co][6], w7 = ws[c][co][7], w8 = ws[c][co][8];
                acc0[co] += a[0][0]*w0 + a[0][1]*w1 + a[0][2]*w2
                          + a[1][0]*w3 + a[1][1]*w4 + a[1][2]*w5
                          + a[2][0]*w6 + a[2][1]*w7 + a[2][2]*w8;
                acc1[co] += a[2][0]*w0 + a[2][1]*w1 + a[2][2]*w2
                          + a[3][0]*w3 + a[3][1]*w4 + a[3][2]*w5
                          + a[4][0]*w6 + a[4][1]*w7 + a[4][2]*w8;
            }
        }
    }

    int oy = oy0 + 2 * ty, ox = ox0 + tx;
#pragma unroll
    for (int co = 0; co < 8; co++) {
        float bz = bias[co0 + co];
        float v0 = acc0[co] + bz, v1 = acc1[co] + bz;
        v0 = v0 > 0.f ? v0 : 0.2f * v0;
        v1 = v1 > 0.f ? v1 : 0.2f * v1;
        size_t o = (((size_t)n * Cout + co0 + co) * Hout + oy) * Wout + ox;
        out[o]        = v0;
        out[o + Wout] = v1;
    }
}

// ---------------- streams/events (created once at load time) ----------------
static cudaStream_t g_sB, g_sC, g_sD, g_sE;
static cudaEvent_t g_ev1[10], g_evB[10], g_ev2[10], g_evD[10], g_evE;
static bool g_streams_ok = [] {
    if (cudaStreamCreateWithFlags(&g_sB, cudaStreamNonBlocking) != cudaSuccess) return false;
    if (cudaStreamCreateWithFlags(&g_sC, cudaStreamNonBlocking) != cudaSuccess) return false;
    if (cudaStreamCreateWithFlags(&g_sD, cudaStreamNonBlocking) != cudaSuccess) return false;
    if (cudaStreamCreateWithFlags(&g_sE, cudaStreamNonBlocking) != cudaSuccess) return false;
    for (int i = 0; i < 10; i++) {
        cudaEventCreateWithFlags(&g_ev1[i], cudaEventDisableTiming);
        cudaEventCreateWithFlags(&g_evB[i], cudaEventDisableTiming);
        cudaEventCreateWithFlags(&g_ev2[i], cudaEventDisableTiming);
        cudaEventCreateWithFlags(&g_evD[i], cudaEventDisableTiming);
    }
    cudaEventCreateWithFlags(&g_evE, cudaEventDisableTiming);
    return true;
}();

extern "C" void kernel_launch(void* const* d_in, const int* in_sizes, int n_in,
                              void* d_out, int out_size)
{
    const float* x   = (const float*)d_in[0];
    const float* W1  = (const float*)d_in[1];
    const float* b1  = (const float*)d_in[2];
    const float* Wg1 = (const float*)d_in[3];
    const float* bg1 = (const float*)d_in[4];
    const float* Wc1 = (const float*)d_in[5];
    const float* bc1 = (const float*)d_in[6];
    const float* W2  = (const float*)d_in[7];
    const float* b2  = (const float*)d_in[8];
    const float* Wg2 = (const float*)d_in[9];
    const float* bg2 = (const float*)d_in[10];
    const float* Wc2 = (const float*)d_in[11];
    const float* bc2 = (const float*)d_in[12];
    const float* W3  = (const float*)d_in[13];
    const float* b3  = (const float*)d_in[14];
    const float* Wg3 = (const float*)d_in[15];
    const float* bg3 = (const float*)d_in[16];
    const float* Wc3 = (const float*)d_in[17];
    const float* bc3 = (const float*)d_in[18];

    float* base = nullptr;
    cudaGetSymbolAddress((void**)&base, g_scratch);

    float* feat1  = base;                   // 5,242,880
    float* outs1  = base + 5242880;         // 20,971,520
    float* feat2  = base + 26214400;        // 5,242,880
    float* outs2  = base + 31457280;        // 7,864,320
    float* feat3  = base + 39321600;        // 1,966,080
    float* outs3  = base + 41287680;        // 1,966,080
    float* gates1 = base + 43253760;        // 4,194,304 (8*128*4096)
    float* gxg1   = base + 47448064;        // 41,943,040
    float* gxc1   = base + 89391104;        // 20,971,520
    float* gxg2   = base + 110362624;       // 15,728,640
    float* gxc2   = base + 126091264;       // 7,864,320
    float* gxg3   = base + 133955584;       // 3,932,160
    float* gxc3   = base + 137887744;       // 1,966,080
    float* gates2 = base + 139853824;       // 1,572,864 (8*192*1024)
    float* gates3 = base + 141426688;       // 393,216   (8*192*256)

    dim3 blk(16, 8);
    cudaStream_t s0 = 0;

    // per-t slice sizes (floats)
    const size_t O1T = 8UL * 64 * 4096;   // outs1 per t = 2,097,152
    const size_t F2T = 8UL * 64 * 1024;   // feat2 per t = 524,288
    const size_t GG2 = 8UL * 192 * 1024;  // gxg2 per t = 1,572,864
    const size_t GC2 = 8UL * 96 * 1024;   // gxc2 per t = 786,432
    const size_t O2T = 8UL * 96 * 1024;   // outs2 per t = 786,432
    const size_t F3T = 8UL * 96 * 256;    // feat3 per t = 196,608
    const size_t GG3 = 8UL * 192 * 256;   // gxg3 per t = 393,216
    const size_t GC3 = 8UL * 96 * 256;    // gxc3 per t = 196,608
    const size_t O3T = 8UL * 96 * 256;    // outs3 per t = 196,608

    // ================= Stage 1 on s0 (saturating) =================
    conv_s2_lrelu<<<dim3(80 * 2, 4, 4), blk, 0, s0>>>(x, W1, b1, feat1,
                                                      1, 16, 128, 128, 16384, 163840);
    conv_pre<<<dim3(80 * 16, 4, 4), blk, 0, s0>>>(feat1, Wg1, bg1, gxg1, 16, 80, 128, 64, 64);
    conv_pre<<<dim3(80 * 8, 4, 4), blk, 0, s0>>>(feat1, Wc1, bc1, gxc1, 16, 80, 64, 64, 64);
    gru_t0<<<(8 * 64 * 4096 + 255) / 256, 256, 0, s0>>>(gxg1, gxc1, outs1, 64, 4096,
                                                        8 * 64 * 4096);
    cudaEventRecord(g_ev1[0], s0);
    for (int t = 1; t < 10; t++) {
        const float* hp = outs1 + (size_t)(t - 1) * O1T;
        float* hn = outs1 + (size_t)t * O1T;
        gru_conv_h<<<dim3(8 * 16, 4, 4), blk, 0, s0>>>(hp, Wg1, gxg1 + (size_t)t * 8 * 128 * 4096,
                                                       gates1, gates1, 16, 80, 64, 128, 64, 64, 0);
        gru_conv_h<<<dim3(8 * 8, 4, 4), blk, 0, s0>>>(hp, Wc1, gxc1 + (size_t)t * O1T,
                                                      gates1, hn, 16, 80, 64, 64, 64, 64, 1);
        cudaEventRecord(g_ev1[t], s0);
    }

    // ================= Stage 2 pre (stream B, per-t, trails stage 1) =========
    for (int t = 0; t < 10; t++) {
        cudaStreamWaitEvent(g_sB, g_ev1[t], 0);
        conv_s2_lrelu<<<dim3(8 * 8, 2, 2), blk, 0, g_sB>>>(outs1 + (size_t)t * O1T, W2, b2,
                                                           feat2 + (size_t)t * F2T,
                                                           64, 64, 64, 64, 0, 64 * 4096);
        conv_pre<<<dim3(8 * 24, 2, 2), blk, 0, g_sB>>>(feat2 + (size_t)t * F2T, Wg2, bg2,
                                                       gxg2 + (size_t)t * GG2,
                                                       64, 160, 192, 32, 32);
        conv_pre<<<dim3(8 * 12, 2, 2), blk, 0, g_sB>>>(feat2 + (size_t)t * F2T, Wc2, bc2,
                                                       gxc2 + (size_t)t * GC2,
                                                       64, 160, 96, 32, 32);
        cudaEventRecord(g_evB[t], g_sB);
    }

    // ================= Stage 2 recurrence (stream C) =================
    cudaStreamWaitEvent(g_sC, g_evB[0], 0);
    gru_t0<<<(int)((O2T + 255) / 256), 256, 0, g_sC>>>(gxg2, gxc2, outs2, 96, 1024, (int)O2T);
    cudaEventRecord(g_ev2[0], g_sC);
    for (int t = 1; t < 10; t++) {
        cudaStreamWaitEvent(g_sC, g_evB[t], 0);
        const float* hp = outs2 + (size_t)(t - 1) * O2T;
        float* hn = outs2 + (size_t)t * O2T;
        gru_conv_h<<<dim3(8 * 24, 2, 2), blk, 0, g_sC>>>(hp, Wg2, gxg2 + (size_t)t * GG2,
                                                         gates2, gates2, 64, 160, 96, 192, 32, 32, 0);
        gru_conv_h<<<dim3(8 * 12, 2, 2), blk, 0, g_sC>>>(hp, Wc2, gxc2 + (size_t)t * GC2,
                                                         gates2, hn, 64, 160, 96, 96, 32, 32, 1);
        cudaEventRecord(g_ev2[t], g_sC);
    }

    // ================= Stage 3 pre (stream D, per-t, trails stage 2) =========
    for (int t = 0; t < 10; t++) {
        cudaStreamWaitEvent(g_sD, g_ev2[t], 0);
        conv_s2_lrelu<<<dim3(8 * 12, 1, 1), blk, 0, g_sD>>>(outs2 + (size_t)t * O2T, W3, b3,
                                                            feat3 + (size_t)t * F3T,
                                                            96, 96, 32, 32, 0, 96 * 1024);
        conv_pre<<<dim3(8 * 24, 1, 1), blk, 0, g_sD>>>(feat3 + (size_t)t * F3T, Wg3, bg3,
                                                       gxg3 + (size_t)t * GG3,
                                                       96, 192, 192, 16, 16);
        conv_pre<<<dim3(8 * 12, 1, 1), blk, 0, g_sD>>>(feat3 + (size_t)t * F3T, Wc3, bc3,
                                                       gxc3 + (size_t)t * GC3,
                                                       96, 192, 96, 16, 16);
        cudaEventRecord(g_evD[t], g_sD);
    }

    // ================= Stage 3 recurrence (stream E) =================
    cudaStreamWaitEvent(g_sE, g_evD[0], 0);
    gru_t0<<<(int)((O3T + 255) / 256), 256, 0, g_sE>>>(gxg3, gxc3, outs3, 96, 256, (int)O3T);
    for (int t = 1; t < 10; t++) {
        cudaStreamWaitEvent(g_sE, g_evD[t], 0);
        const float* hp = outs3 + (size_t)(t - 1) * O3T;
        float* hn = outs3 + (size_t)t * O3T;
        gru_conv_h<<<dim3(8 * 24, 1, 1), blk, 0, g_sE>>>(hp, Wg3, gxg3 + (size_t)t * GG3,
                                                         gates3, gates3, 96, 192, 96, 192, 16, 16, 0);
        gru_conv_h<<<dim3(8 * 12, 1, 1), blk, 0, g_sE>>>(hp, Wc3, gxc3 + (size_t)t * GC3,
                                                         gates3, hn, 96, 192, 96, 96, 16, 16, 1);
    }
    cudaEventRecord(g_evE, g_sE);

    // ---------------- Join all forked streams back into s0 ----------------
    cudaStreamWaitEvent(s0, g_evB[9], 0);
    cudaStreamWaitEvent(s0, g_ev2[9], 0);
    cudaStreamWaitEvent(s0, g_evD[9], 0);
    cudaStreamWaitEvent(s0, g_evE, 0);

    // ---------------- Assemble output: (h1, h2, h3) flattened ----------------
    float* out = (float*)d_out;
    cudaMemcpyAsync(out, outs1 + 9UL * O1T,
                    O1T * sizeof(float), cudaMemcpyDeviceToDevice, s0);
    cudaMemcpyAsync(out + 2097152, outs2 + 9UL * O2T,
                    O2T * sizeof(float), cudaMemcpyDeviceToDevice, s0);
    cudaMemcpyAsync(out + 2097152 + 786432, outs3 + 9UL * O3T,
                    O3T * sizeof(float), cudaMemcpyDeviceToDevice, s0);
}

// round 13
// speedup vs baseline: 2.1568x; 1.0644x over previous
#include <cuda_runtime.h>
#include <math.h>

#define TS 16
#define CSTEP 8
#define CSTEP2 4

// Scratch (fp32): feat/outs/gates + hoisted x-part conv results
__device__ float g_scratch[141819904];

__device__ __forceinline__ float sigf(float x) { return 1.f / (1.f + __expf(-x)); }
__device__ __forceinline__ float ftanh(float x) {
    float e = __expf(2.f * x);
    return 1.f - 2.f / (e + 1.f);
}

// ---------------------------------------------------------------------------
// Tile loader: 8 channel planes of 18x19 (halo, zero-pad), strided by 128
// threads with incremental index arithmetic (identical addresses/order to the
// R11 loader). dst = flattened [8][18][19]. withR: multiply by r-gate plane.
// ---------------------------------------------------------------------------
__device__ __forceinline__ void load_tile8(float* __restrict__ dst,
                                           const float* __restrict__ src,
                                           const float* __restrict__ rs,
                                           int oy0, int ox0, int H, int W, int HW,
                                           int tid, bool withR)
{
    int iy = tid / 18, ix = tid % 18;
    int gy = oy0 - 1 + iy, gx = ox0 - 1 + ix;
    int sof = iy * 19 + ix;
    int goff = gy * W + gx;
    if (withR) {
        for (int i = tid; i < CSTEP * 324; i += 128) {
            float v = 0.f;
            if ((unsigned)gy < (unsigned)H && (unsigned)gx < (unsigned)W)
                v = src[goff] * rs[goff];
            dst[sof] = v;
            ix += 2; iy += 7; gy += 7; gx += 2;
            goff += 7 * W + 2; sof += 135;
            if (ix >= 18) { ix -= 18; gx -= 18; iy += 1; gy += 1;
                            goff += W - 18; sof += 1; }
            if (iy >= 18) { iy -= 18; gy -= 18; goff += HW - 18 * W; }
        }
    } else {
        for (int i = tid; i < CSTEP * 324; i += 128) {
            float v = 0.f;
            if ((unsigned)gy < (unsigned)H && (unsigned)gx < (unsigned)W)
                v = src[goff];
            dst[sof] = v;
            ix += 2; iy += 7; gy += 7; gx += 2;
            goff += 7 * W + 2; sof += 135;
            if (ix >= 18) { ix -= 18; gx -= 18; iy += 1; gy += 1;
                            goff += W - 18; sof += 1; }
            if (iy >= 18) { iy -= 18; gy -= 18; goff += HW - 18 * W; }
        }
    }
}

// weights loader: 8c x 8co x 9 into flattened [8][8][12]
__device__ __forceinline__ void load_ws8(float* __restrict__ wdst,
                                         const float* __restrict__ Wt,
                                         int co0, int CinTot, int woff, int ci0,
                                         int tid)
{
    for (int i = tid; i < CSTEP * 72; i += 128) {
        int c = i / 72, r = i % 72;
        int co = r / 9, kk = r % 9;
        wdst[c * 96 + co * 12 + kk] =
            Wt[((size_t)(co0 + co) * CinTot + woff + ci0 + c) * 9 + kk];
    }
}

// compute one 8-channel chunk from smem buffers (unchanged math/order)
__device__ __forceinline__ void compute_chunk(const float (* __restrict__ tile)[18][19],
                                              const float (* __restrict__ ws)[8][12],
                                              int tx, int ty,
                                              float acc0[8], float acc1[8])
{
#pragma unroll
    for (int c = 0; c < CSTEP; c++) {
        float a[4][3];
#pragma unroll
        for (int i = 0; i < 4; i++)
#pragma unroll
            for (int j = 0; j < 3; j++)
                a[i][j] = tile[c][2 * ty + i][tx + j];
#pragma unroll
        for (int co = 0; co < 8; co++) {
            float4 wa = *(const float4*)&ws[c][co][0];
            float4 wb = *(const float4*)&ws[c][co][4];
            float w8  = ws[c][co][8];
            acc0[co] += a[0][0]*wa.x + a[0][1]*wa.y + a[0][2]*wa.z
                      + a[1][0]*wa.w + a[1][1]*wb.x + a[1][2]*wb.y
                      + a[2][0]*wb.z + a[2][1]*wb.w + a[2][2]*w8;
            acc1[co] += a[1][0]*wa.x + a[1][1]*wa.y + a[1][2]*wa.z
                      + a[2][0]*wa.w + a[2][1]*wb.x + a[2][2]*wb.y
                      + a[3][0]*wb.z + a[3][1]*wb.w + a[3][2]*w8;
        }
    }
}

// ---------------------------------------------------------------------------
// Batched stride-1 3x3 conv (pad 1), double-buffered smem pipeline.
// grid: (N * Cout/8, H/16, W/16), block (16,8)
// ---------------------------------------------------------------------------
__global__ __launch_bounds__(128)
void conv_pre(const float* __restrict__ in, const float* __restrict__ Wt,
              const float* __restrict__ bias, float* __restrict__ out,
              int Cin, int CinTot, int Cout, int H, int W)
{
    int coutBlocks = Cout >> 3;
    int n   = blockIdx.x / coutBlocks;
    int co0 = (blockIdx.x % coutBlocks) * 8;
    int oy0 = blockIdx.y * TS;
    int ox0 = blockIdx.z * TS;
    int tx = threadIdx.x, ty = threadIdx.y;
    int tid = ty * 16 + tx;

    __shared__ float tile[2][CSTEP][18][19];
    __shared__ __align__(16) float ws[2][CSTEP][8][12];

    int HW = H * W;
    const float* inN = in + (size_t)n * Cin * HW;

    float acc0[8], acc1[8];
#pragma unroll
    for (int i = 0; i < 8; i++) { acc0[i] = 0.f; acc1[i] = 0.f; }

    // prologue: fill buffer 0 with chunk 0
    load_tile8(&tile[0][0][0][0], inN, nullptr, oy0, ox0, H, W, HW, tid, false);
    load_ws8(&ws[0][0][0][0], Wt, co0, CinTot, 0, 0, tid);

    int cur = 0;
    for (int ci0 = 0; ci0 < Cin; ci0 += CSTEP) {
        __syncthreads();
        int nxt = ci0 + CSTEP;
        if (nxt < Cin) {
            load_tile8(&tile[cur ^ 1][0][0][0], inN + (size_t)nxt * HW, nullptr,
                       oy0, ox0, H, W, HW, tid, false);
            load_ws8(&ws[cur ^ 1][0][0][0], Wt, co0, CinTot, 0, nxt, tid);
        }
        compute_chunk(tile[cur], ws[cur], tx, ty, acc0, acc1);
        cur ^= 1;
    }

    int oy = oy0 + 2 * ty, ox = ox0 + tx;
#pragma unroll
    for (int co = 0; co < 8; co++) {
        float bz = bias[co0 + co];
        size_t o = ((size_t)n * Cout + co0 + co) * HW + (size_t)oy * W + ox;
        out[o]     = acc0[co] + bz;
        out[o + W] = acc1[co] + bz;
    }
}

// ---------------------------------------------------------------------------
// Recurrent h-part conv (t >= 1), double-buffered. mode 0: gates -> sigmoid.
// mode 1: cand (r*h in loader) -> GRU update. Seeded by pre (= bias + x-part).
// grid: (B * Cout/8, H/16, W/16)
// ---------------------------------------------------------------------------
__global__ __launch_bounds__(128)
void gru_conv_h(const float* __restrict__ hprev, const float* __restrict__ Wt,
                const float* __restrict__ pre, const float* __restrict__ gatesIn,
                float* __restrict__ out,
                int Cx, int CinTot, int Ch, int Cout, int H, int W, int mode)
{
    int coutBlocks = Cout >> 3;
    int b   = blockIdx.x / coutBlocks;
    int co0 = (blockIdx.x % coutBlocks) * 8;
    int oy0 = blockIdx.y * TS;
    int ox0 = blockIdx.z * TS;
    int tx = threadIdx.x, ty = threadIdx.y;
    int tid = ty * 16 + tx;

    __shared__ float tile[2][CSTEP][18][19];
    __shared__ __align__(16) float ws[2][CSTEP][8][12];

    int HW = H * W;
    const float* hbase = hprev + (size_t)b * Ch * HW;
    const float* rbase = gatesIn + (size_t)b * 2 * Ch * HW;
    bool withR = (mode != 0);

    float acc0[8], acc1[8];
#pragma unroll
    for (int i = 0; i < 8; i++) { acc0[i] = 0.f; acc1[i] = 0.f; }

    load_tile8(&tile[0][0][0][0], hbase, rbase, oy0, ox0, H, W, HW, tid, withR);
    load_ws8(&ws[0][0][0][0], Wt, co0, CinTot, Cx, 0, tid);

    int cur = 0;
    for (int ci0 = 0; ci0 < Ch; ci0 += CSTEP) {
        __syncthreads();
        int nxt = ci0 + CSTEP;
        if (nxt < Ch) {
            load_tile8(&tile[cur ^ 1][0][0][0], hbase + (size_t)nxt * HW,
                       rbase + (size_t)nxt * HW, oy0, ox0, H, W, HW, tid, withR);
            load_ws8(&ws[cur ^ 1][0][0][0], Wt, co0, CinTot, Cx, nxt, tid);
        }
        compute_chunk(tile[cur], ws[cur], tx, ty, acc0, acc1);
        cur ^= 1;
    }

    int oy = oy0 + 2 * ty, ox = ox0 + tx;
    if (mode == 0) {
#pragma unroll
        for (int co = 0; co < 8; co++) {
            size_t po = ((size_t)b * Cout + co0 + co) * HW + (size_t)oy * W + ox;
            float p0 = pre[po], p1 = pre[po + W];
            size_t o = (((size_t)b * Cout + co0 + co) * H + oy) * W + ox;
            out[o]     = sigf(acc0[co] + p0);
            out[o + W] = sigf(acc1[co] + p1);
        }
    } else {
#pragma unroll
        for (int co = 0; co < 8; co++) {
            int cc = co0 + co;
            size_t po = ((size_t)b * Cout + cc) * HW + (size_t)oy * W + ox;
            float p0 = pre[po], p1 = pre[po + W];
            size_t zo = (((size_t)b * 2 * Ch + Ch + cc) * H + oy) * W + ox;
            float z0 = gatesIn[zo], z1 = gatesIn[zo + W];
            size_t ho = (((size_t)b * Ch + cc) * H + oy) * W + ox;
            float h0v = hprev[ho], h1v = hprev[ho + W];
            out[ho]     = z0 * h0v + (1.f - z0) * ftanh(acc0[co] + p0);
            out[ho + W] = z1 * h1v + (1.f - z1) * ftanh(acc1[co] + p1);
        }
    }
}

// ---------------------------------------------------------------------------
// t = 0 step (h == 0): hn = (1 - sigmoid(z_pre)) * tanh(c_pre), elementwise.
// ---------------------------------------------------------------------------
__global__ void gru_t0(const float* __restrict__ gz, const float* __restrict__ gc,
                       float* __restrict__ hn, int Ch, int HW, int total)
{
    int i = blockIdx.x * 256 + threadIdx.x;
    if (i >= total) return;
    int b = i / (Ch * HW);
    float z = sigf(gz[(size_t)i + (size_t)(b + 1) * Ch * HW]);
    hn[i] = (1.f - z) * ftanh(gc[i]);
}

// ---------------------------------------------------------------------------
// Stride-2 3x3 conv (pad 1) + leaky relu(0.2).
// ---------------------------------------------------------------------------
__global__ void conv_s2_lrelu(const float* __restrict__ in, const float* __restrict__ Wt,
                              const float* __restrict__ bias, float* __restrict__ out,
                              int Cin, int Cout, int Hin, int Win, int sOuter, int sInner)
{
    int coutBlocks = Cout >> 3;
    int n  = blockIdx.x / coutBlocks;
    int cb = blockIdx.x % coutBlocks;
    int co0 = cb * 8;
    int t = n / 8, b = n % 8;
    const float* inN = in + (size_t)t * sOuter + (size_t)b * sInner;
    int Hout = Hin >> 1, Wout = Win >> 1;
    int oy0 = blockIdx.y * TS, ox0 = blockIdx.z * TS;
    int tx = threadIdx.x, ty = threadIdx.y;
    int tid = ty * 16 + tx;

    __shared__ float tile[CSTEP2][33][35];
    __shared__ float ws[CSTEP2][8][9];

    float acc0[8], acc1[8];
#pragma unroll
    for (int i = 0; i < 8; i++) { acc0[i] = 0.f; acc1[i] = 0.f; }

    for (int ci0 = 0; ci0 < Cin; ci0 += CSTEP2) {
        __syncthreads();
        for (int i = tid; i < CSTEP2 * 1089; i += 128) {
            int c = i / 1089, p = i % 1089;
            int ly = p / 33, lx = p % 33;
            int gy = 2 * oy0 - 1 + ly, gx = 2 * ox0 - 1 + lx;
            float v = 0.f;
            int ci = ci0 + c;
            if (ci < Cin && gy >= 0 && gy < Hin && gx >= 0 && gx < Win)
                v = inN[((size_t)ci * Hin + gy) * Win + gx];
            tile[c][ly][lx] = v;
        }
        for (int i = tid; i < CSTEP2 * 72; i += 128) {
            int c = i / 72, r = i % 72;
            int co = r / 9, k = r % 9;
            float wv = 0.f;
            if (ci0 + c < Cin)
                wv = Wt[((size_t)(co0 + co) * Cin + (ci0 + c)) * 9 + k];
            ws[c][co][k] = wv;
        }
        __syncthreads();

#pragma unroll
        for (int c = 0; c < CSTEP2; c++) {
            float a[5][3];
#pragma unroll
            for (int i = 0; i < 5; i++)
#pragma unroll
                for (int j = 0; j < 3; j++)
                    a[i][j] = tile[c][4 * ty + i][2 * tx + j];
#pragma unroll
            for (int co = 0; co < 8; co++) {
                float w0 = ws[c][co][0], w1 = ws[c][co][1], w2 = ws[c][co][2];
                float w3 = ws[c][co][3], w4 = ws[c][co][4], w5 = ws[c][co][5];
                float w6 = ws[c][co][6], w7 = ws[c][co][7], w8 = ws[c][co][8];
                acc0[co] += a[0][0]*w0 + a[0][1]*w1 + a[0][2]*w2
                          + a[1][0]*w3 + a[1][1]*w4 + a[1][2]*w5
                          + a[2][0]*w6 + a[2][1]*w7 + a[2][2]*w8;
                acc1[co] += a[2][0]*w0 + a[2][1]*w1 + a[2][2]*w2
                          + a[3][0]*w3 + a[3][1]*w4 + a[3][2]*w5
                          + a[4][0]*w6 + a[4][1]*w7 + a[4][2]*w8;
            }
        }
    }

    int oy = oy0 + 2 * ty, ox = ox0 + tx;
#pragma unroll
    for (int co = 0; co < 8; co++) {
        float bz = bias[co0 + co];
        float v0 = acc0[co] + bz, v1 = acc1[co] + bz;
        v0 = v0 > 0.f ? v0 : 0.2f * v0;
        v1 = v1 > 0.f ? v1 : 0.2f * v1;
        size_t o = (((size_t)n * Cout + co0 + co) * Hout + oy) * Wout + ox;
        out[o]        = v0;
        out[o + Wout] = v1;
    }
}

// ---------------- streams/events (created once at load time) ----------------
static cudaStream_t g_sB, g_sC, g_sD, g_sE;
static cudaEvent_t g_ev1[10], g_evB[10], g_ev2[10], g_evD[10], g_evE;
static bool g_streams_ok = [] {
    if (cudaStreamCreateWithFlags(&g_sB, cudaStreamNonBlocking) != cudaSuccess) return false;
    if (cudaStreamCreateWithFlags(&g_sC, cudaStreamNonBlocking) != cudaSuccess) return false;
    if (cudaStreamCreateWithFlags(&g_sD, cudaStreamNonBlocking) != cudaSuccess) return false;
    if (cudaStreamCreateWithFlags(&g_sE, cudaStreamNonBlocking) != cudaSuccess) return false;
    for (int i = 0; i < 10; i++) {
        cudaEventCreateWithFlags(&g_ev1[i], cudaEventDisableTiming);
        cudaEventCreateWithFlags(&g_evB[i], cudaEventDisableTiming);
        cudaEventCreateWithFlags(&g_ev2[i], cudaEventDisableTiming);
        cudaEventCreateWithFlags(&g_evD[i], cudaEventDisableTiming);
    }
    cudaEventCreateWithFlags(&g_evE, cudaEventDisableTiming);
    return true;
}();

extern "C" void kernel_launch(void* const* d_in, const int* in_sizes, int n_in,
                              void* d_out, int out_size)
{
    const float* x   = (const float*)d_in[0];
    const float* W1  = (const float*)d_in[1];
    const float* b1  = (const float*)d_in[2];
    const float* Wg1 = (const float*)d_in[3];
    const float* bg1 = (const float*)d_in[4];
    const float* Wc1 = (const float*)d_in[5];
    const float* bc1 = (const float*)d_in[6];
    const float* W2  = (const float*)d_in[7];
    const float* b2  = (const float*)d_in[8];
    const float* Wg2 = (const float*)d_in[9];
    const float* bg2 = (const float*)d_in[10];
    const float* Wc2 = (const float*)d_in[11];
    const float* bc2 = (const float*)d_in[12];
    const float* W3  = (const float*)d_in[13];
    const float* b3  = (const float*)d_in[14];
    const float* Wg3 = (const float*)d_in[15];
    const float* bg3 = (const float*)d_in[16];
    const float* Wc3 = (const float*)d_in[17];
    const float* bc3 = (const float*)d_in[18];

    float* base = nullptr;
    cudaGetSymbolAddress((void**)&base, g_scratch);

    float* feat1  = base;                   // 5,242,880
    float* outs1  = base + 5242880;         // 20,971,520
    float* feat2  = base + 26214400;        // 5,242,880
    float* outs2  = base + 31457280;        // 7,864,320
    float* feat3  = base + 39321600;        // 1,966,080
    float* outs3  = base + 41287680;        // 1,966,080
    float* gates1 = base + 43253760;        // 4,194,304 (8*128*4096)
    float* gxg1   = base + 47448064;        // 41,943,040
    float* gxc1   = base + 89391104;        // 20,971,520
    float* gxg2   = base + 110362624;       // 15,728,640
    float* gxc2   = base + 126091264;       // 7,864,320
    float* gxg3   = base + 133955584;       // 3,932,160
    float* gxc3   = base + 137887744;       // 1,966,080
    float* gates2 = base + 139853824;       // 1,572,864 (8*192*1024)
    float* gates3 = base + 141426688;       // 393,216   (8*192*256)

    dim3 blk(16, 8);
    cudaStream_t s0 = 0;

    const size_t O1T = 8UL * 64 * 4096;
    const size_t F2T = 8UL * 64 * 1024;
    const size_t GG2 = 8UL * 192 * 1024;
    const size_t GC2 = 8UL * 96 * 1024;
    const size_t O2T = 8UL * 96 * 1024;
    const size_t F3T = 8UL * 96 * 256;
    const size_t GG3 = 8UL * 192 * 256;
    const size_t GC3 = 8UL * 96 * 256;
    const size_t O3T = 8UL * 96 * 256;

    // ================= Stage 1 on s0 (saturating) =================
    conv_s2_lrelu<<<dim3(80 * 2, 4, 4), blk, 0, s0>>>(x, W1, b1, feat1,
                                                      1, 16, 128, 128, 16384, 163840);
    conv_pre<<<dim3(80 * 16, 4, 4), blk, 0, s0>>>(feat1, Wg1, bg1, gxg1, 16, 80, 128, 64, 64);
    conv_pre<<<dim3(80 * 8, 4, 4), blk, 0, s0>>>(feat1, Wc1, bc1, gxc1, 16, 80, 64, 64, 64);
    gru_t0<<<(8 * 64 * 4096 + 255) / 256, 256, 0, s0>>>(gxg1, gxc1, outs1, 64, 4096,
                                                        8 * 64 * 4096);
    cudaEventRecord(g_ev1[0], s0);
    for (int t = 1; t < 10; t++) {
        const float* hp = outs1 + (size_t)(t - 1) * O1T;
        float* hn = outs1 + (size_t)t * O1T;
        gru_conv_h<<<dim3(8 * 16, 4, 4), blk, 0, s0>>>(hp, Wg1, gxg1 + (size_t)t * 8 * 128 * 4096,
                                                       gates1, gates1, 16, 80, 64, 128, 64, 64, 0);
        gru_conv_h<<<dim3(8 * 8, 4, 4), blk, 0, s0>>>(hp, Wc1, gxc1 + (size_t)t * O1T,
                                                      gates1, hn, 16, 80, 64, 64, 64, 64, 1);
        cudaEventRecord(g_ev1[t], s0);
    }

    // ================= Stage 2 pre (stream B) =================
    for (int t = 0; t < 10; t++) {
        cudaStreamWaitEvent(g_sB, g_ev1[t], 0);
        conv_s2_lrelu<<<dim3(8 * 8, 2, 2), blk, 0, g_sB>>>(outs1 + (size_t)t * O1T, W2, b2,
                                                           feat2 + (size_t)t * F2T,
                                                           64, 64, 64, 64, 0, 64 * 4096);
        conv_pre<<<dim3(8 * 24, 2, 2), blk, 0, g_sB>>>(feat2 + (size_t)t * F2T, Wg2, bg2,
                                                       gxg2 + (size_t)t * GG2,
                                                       64, 160, 192, 32, 32);
        conv_pre<<<dim3(8 * 12, 2, 2), blk, 0, g_sB>>>(feat2 + (size_t)t * F2T, Wc2, bc2,
                                                       gxc2 + (size_t)t * GC2,
                                                       64, 160, 96, 32, 32);
        cudaEventRecord(g_evB[t], g_sB);
    }

    // ================= Stage 2 recurrence (stream C) =================
    cudaStreamWaitEvent(g_sC, g_evB[0], 0);
    gru_t0<<<(int)((O2T + 255) / 256), 256, 0, g_sC>>>(gxg2, gxc2, outs2, 96, 1024, (int)O2T);
    cudaEventRecord(g_ev2[0], g_sC);
    for (int t = 1; t < 10; t++) {
        cudaStreamWaitEvent(g_sC, g_evB[t], 0);
        const float* hp = outs2 + (size_t)(t - 1) * O2T;
        float* hn = outs2 + (size_t)t * O2T;
        gru_conv_h<<<dim3(8 * 24, 2, 2), blk, 0, g_sC>>>(hp, Wg2, gxg2 + (size_t)t * GG2,
                                                         gates2, gates2, 64, 160, 96, 192, 32, 32, 0);
        gru_conv_h<<<dim3(8 * 12, 2, 2), blk, 0, g_sC>>>(hp, Wc2, gxc2 + (size_t)t * GC2,
                                                         gates2, hn, 64, 160, 96, 96, 32, 32, 1);
        cudaEventRecord(g_ev2[t], g_sC);
    }

    // ================= Stage 3 pre (stream D) =================
    for (int t = 0; t < 10; t++) {
        cudaStreamWaitEvent(g_sD, g_ev2[t], 0);
        conv_s2_lrelu<<<dim3(8 * 12, 1, 1), blk, 0, g_sD>>>(outs2 + (size_t)t * O2T, W3, b3,
                                                            feat3 + (size_t)t * F3T,
                                                            96, 96, 32, 32, 0, 96 * 1024);
        conv_pre<<<dim3(8 * 24, 1, 1), blk, 0, g_sD>>>(feat3 + (size_t)t * F3T, Wg3, bg3,
                                                       gxg3 + (size_t)t * GG3,
                                                       96, 192, 192, 16, 16);
        conv_pre<<<dim3(8 * 12, 1, 1), blk, 0, g_sD>>>(feat3 + (size_t)t * F3T, Wc3, bc3,
                                                       gxc3 + (size_t)t * GC3,
                                                       96, 192, 96, 16, 16);
        cudaEventRecord(g_evD[t], g_sD);
    }

    // ================= Stage 3 recurrence (stream E) =================
    cudaStreamWaitEvent(g_sE, g_evD[0], 0);
    gru_t0<<<(int)((O3T + 255) / 256), 256, 0, g_sE>>>(gxg3, gxc3, outs3, 96, 256, (int)O3T);
    for (int t = 1; t < 10; t++) {
        cudaStreamWaitEvent(g_sE, g_evD[t], 0);
        const float* hp = outs3 + (size_t)(t - 1) * O3T;
        float* hn = outs3 + (size_t)t * O3T;
        gru_conv_h<<<dim3(8 * 24, 1, 1), blk, 0, g_sE>>>(hp, Wg3, gxg3 + (size_t)t * GG3,
                                                         gates3, gates3, 96, 192, 96, 192, 16, 16, 0);
        gru_conv_h<<<dim3(8 * 12, 1, 1), blk, 0, g_sE>>>(hp, Wc3, gxc3 + (size_t)t * GC3,
                                                         gates3, hn, 96, 192, 96, 96, 16, 16, 1);
    }
    cudaEventRecord(g_evE, g_sE);

    // ---------------- Join all forked streams back into s0 ----------------
    cudaStreamWaitEvent(s0, g_evB[9], 0);
    cudaStreamWaitEvent(s0, g_ev2[9], 0);
    cudaStreamWaitEvent(s0, g_evD[9], 0);
    cudaStreamWaitEvent(s0, g_evE, 0);

    // ---------------- Assemble output: (h1, h2, h3) flattened ----------------
    float* out = (float*)d_out;
    cudaMemcpyAsync(out, outs1 + 9UL * O1T,
                    O1T * sizeof(float), cudaMemcpyDeviceToDevice, s0);
    cudaMemcpyAsync(out + 2097152, outs2 + 9UL * O2T,
                    O2T * sizeof(float), cudaMemcpyDeviceToDevice, s0);
    cudaMemcpyAsync(out + 2097152 + 786432, outs3 + 9UL * O3T,
                    O3T * sizeof(float), cudaMemcpyDeviceToDevice, s0);
}